// round 8
// baseline (speedup 1.0000x reference)
#include <cuda_runtime.h>
#include <cstdint>

#define B_ 2
#define N_ 2048
#define L_ 2048
#define D_ 1024
#define H_ 16
#define HD_ 64
#define LOG2E 1.4426950408889634f
#define SCALE_Q (0.125f * LOG2E)
#define MASKBIAS (-2.0e30f)
#define MINIT (-1.0e30f)

__device__ float g_Q[(size_t)B_ * H_ * N_ * HD_];
__device__ float g_K[(size_t)B_ * H_ * L_ * HD_];
__device__ float g_V[(size_t)B_ * H_ * L_ * HD_];
__device__ float g_O[(size_t)B_ * N_ * D_];
__device__ unsigned char g_mask[B_ * L_];

__device__ __forceinline__ uint32_t f2tf(float x) {
    uint32_t r; asm("cvt.rna.tf32.f32 %0, %1;" : "=r"(r) : "f"(x)); return r;
}
__device__ __forceinline__ float ex2f(float x) {
    float r; asm("ex2.approx.ftz.f32 %0, %1;" : "=f"(r) : "f"(x)); return r;
}
__device__ __forceinline__ float4 cvt4(float4 v) {
    return make_float4(__uint_as_float(f2tf(v.x)), __uint_as_float(f2tf(v.y)),
                       __uint_as_float(f2tf(v.z)), __uint_as_float(f2tf(v.w)));
}
#define MMA_TF32(C, A, Bf) \
    asm volatile("mma.sync.aligned.m16n8k8.row.col.f32.tf32.tf32.f32 " \
        "{%0,%1,%2,%3},{%4,%5,%6,%7},{%8,%9},{%0,%1,%2,%3};" \
        : "+f"((C)[0]), "+f"((C)[1]), "+f"((C)[2]), "+f"((C)[3]) \
        : "r"((A)[0]), "r"((A)[1]), "r"((A)[2]), "r"((A)[3]), "r"((Bf)[0]), "r"((Bf)[1]))

// ---------------------------------------------------------------------------
__global__ void mask_prep(const void* __restrict__ mraw)
{
    __shared__ int s_isf, s_nb;
    const int t = threadIdx.x;
    if (t == 0) { s_isf = 0; s_nb = 0; }
    __syncthreads();
    const int* ip = (const int*)mraw;
    int v = ip[t];
    if (v == 0x3F800000) atomicExch(&s_isf, 1);
    if (v != 0 && v != 1) atomicExch(&s_nb, 1);
    __syncthreads();
    int mode = s_isf ? 2 : (s_nb ? 1 : 0);
    const unsigned char* bp = (const unsigned char*)mraw;
    const float* fp = (const float*)mraw;
    for (int i = t; i < B_ * L_; i += 1024) {
        unsigned char mv;
        if (mode == 0)      mv = ip[i] != 0;
        else if (mode == 1) mv = bp[i] != 0;
        else                mv = fp[i] != 0.0f;
        g_mask[i] = mv;
    }
}

// ---------------------------------------------------------------------------
// tf32 mma.sync GEMM, warp tile 64x64, double-buffered smem, 1 sync/stage.
// CTA 128(M) x 256(N), BK=16, 256 threads = 8 warps (2m x 4n).
// MODE 0:Q(*SCALE_Q, head-major) 1:K 2:V 3:out-proj (A = g_O).
// ---------------------------------------------------------------------------
#define SA 20
#define SB 264
#define PR_SMEM ((2 * 128 * SA + 2 * 16 * SB) * 4)   // 54272 B

template <int MODE>
__global__ void __launch_bounds__(256, 1)
proj64(const float* __restrict__ A, const float* __restrict__ W,
       const float* __restrict__ bias, float* __restrict__ Cout)
{
    extern __shared__ float sm[];
    float* As = sm;                    // 2 x 128*SA
    float* Bs = sm + 2 * 128 * SA;     // 2 x 16*SB

    const float* Ap = (MODE == 3) ? (const float*)g_O : A;
    const int tid = threadIdx.x;
    const int lane = tid & 31;
    const int wid = tid >> 5;
    const int g = lane >> 2, t = lane & 3;
    const int wm = wid & 1, wn = wid >> 1;
    const int m0 = blockIdx.y * 128, n0 = blockIdx.x * 256;

    const int arow = tid >> 2, akc = (tid & 3) * 4;
    const int brow = tid >> 6, bnc = (tid & 63) * 4;
    const float* aP0 = Ap + (size_t)(m0 + arow) * D_ + akc;
    const float* aP1 = aP0 + (size_t)64 * D_;
    const float* bP = W + (size_t)brow * D_ + n0 + bnc;

    float c[4][8][4];
#pragma unroll
    for (int i = 0; i < 4; i++)
#pragma unroll
        for (int j = 0; j < 8; j++)
#pragma unroll
            for (int k = 0; k < 4; k++) c[i][j][k] = 0.0f;

    float4 ra0 = *(const float4*)aP0;
    float4 ra1 = *(const float4*)aP1;
    float4 rb[4];
#pragma unroll
    for (int q = 0; q < 4; q++) rb[q] = *(const float4*)(bP + (size_t)(4 * q) * D_);

    for (int kt = 0; kt < 64; kt++) {
        float* Asb = As + (kt & 1) * 128 * SA;
        float* Bsb = Bs + (kt & 1) * 16 * SB;
        // store tile kt (regs -> smem buffer kt&1)
        *(float4*)&Asb[arow * SA + akc]        = cvt4(ra0);
        *(float4*)&Asb[(arow + 64) * SA + akc] = cvt4(ra1);
#pragma unroll
        for (int q = 0; q < 4; q++)
            *(float4*)&Bsb[(brow + 4 * q) * SB + bnc] = cvt4(rb[q]);
        // prefetch tile kt+1
        if (kt < 63) {
            size_t oA = (size_t)(kt + 1) * 16;
            ra0 = *(const float4*)(aP0 + oA);
            ra1 = *(const float4*)(aP1 + oA);
#pragma unroll
            for (int q = 0; q < 4; q++)
                rb[q] = *(const float4*)(bP + (size_t)((kt + 1) * 16 + 4 * q) * D_);
        }
        __syncthreads();   // buffer kt&1 ready; prior reads of it (iter kt-2) long done
#pragma unroll
        for (int ks = 0; ks < 2; ks++) {
            const int k0 = ks * 8;
            uint32_t a[4][4];
#pragma unroll
            for (int mt = 0; mt < 4; mt++) {
                int r = wm * 64 + mt * 16 + g;
                a[mt][0] = __float_as_uint(Asb[r * SA + k0 + t]);
                a[mt][1] = __float_as_uint(Asb[(r + 8) * SA + k0 + t]);
                a[mt][2] = __float_as_uint(Asb[r * SA + k0 + t + 4]);
                a[mt][3] = __float_as_uint(Asb[(r + 8) * SA + k0 + t + 4]);
            }
#pragma unroll
            for (int nt = 0; nt < 8; nt++) {
                int n = wn * 64 + nt * 8 + g;
                uint32_t b[2];
                b[0] = __float_as_uint(Bsb[(k0 + t) * SB + n]);
                b[1] = __float_as_uint(Bsb[(k0 + t + 4) * SB + n]);
                MMA_TF32(c[0][nt], a[0], b);
                MMA_TF32(c[1][nt], a[1], b);
                MMA_TF32(c[2][nt], a[2], b);
                MMA_TF32(c[3][nt], a[3], b);
            }
        }
        // no trailing sync: next iter writes the OTHER buffer; the sync above
        // (next iteration) orders those writes after this iteration's reads.
    }

    // epilogue
#pragma unroll
    for (int mt = 0; mt < 4; mt++) {
        int r0 = m0 + wm * 64 + mt * 16 + g;
        int r1 = r0 + 8;
#pragma unroll
        for (int nt = 0; nt < 8; nt++) {
            int col = n0 + wn * 64 + nt * 8 + 2 * t;
            float2 bb = *(const float2*)&bias[col];
            float v00 = c[mt][nt][0] + bb.x, v01 = c[mt][nt][1] + bb.y;
            float v10 = c[mt][nt][2] + bb.x, v11 = c[mt][nt][3] + bb.y;
            if (MODE == 0) {
                v00 *= SCALE_Q; v01 *= SCALE_Q; v10 *= SCALE_Q; v11 *= SCALE_Q;
            }
            if (MODE == 3) {
                *(float2*)&Cout[(size_t)r0 * D_ + col] = make_float2(v00, v01);
                *(float2*)&Cout[(size_t)r1 * D_ + col] = make_float2(v10, v11);
            } else {
                float* dst = (MODE == 0) ? g_Q : (MODE == 1) ? g_K : g_V;
                int hh = col >> 6, hd = col & 63;
                {
                    int bb2 = r0 >> 11, n = r0 & 2047;
                    *(float2*)&dst[(((size_t)(bb2 * H_ + hh)) * 2048 + n) * HD_ + hd] =
                        make_float2(v00, v01);
                }
                {
                    int bb2 = r1 >> 11, n = r1 & 2047;
                    *(float2*)&dst[(((size_t)(bb2 * H_ + hh)) * 2048 + n) * HD_ + hd] =
                        make_float2(v10, v11);
                }
            }
        }
    }
}

// ---------------------------------------------------------------------------
// Flash attention: CTA = 128 queries x (b,h); 4 warps, warp tile 32q x 64kv.
// Q fragments hoisted to registers (loop-invariant). Per-warp private P.
// smem: Qs[128][68] | Ks[64][68] | Vs[64][72] | Ps[4][32][68] | Mb[64]
// ---------------------------------------------------------------------------
#define SQ 68
#define SV 72
#define PWS (32 * SQ)
#define ATTN_SMEM ((128 * SQ + 64 * SQ + 64 * SV + 4 * PWS + 64) * 4)

__global__ void __launch_bounds__(128, 2)
attn2()
{
    extern __shared__ float sm[];
    float* Qs = sm;                  // 128*68
    float* Ks = Qs + 128 * SQ;       // 64*68
    float* Vs = Ks + 64 * SQ;        // 64*72
    float* Ps = Vs + 64 * SV;        // 4*32*68
    float* Mb = Ps + 4 * PWS;        // 64

    const int tid = threadIdx.x;
    const int lane = tid & 31, wid = tid >> 5;
    const int g = lane >> 2, t = lane & 3;
    const int bh = blockIdx.y;
    const int b = bh >> 4, h = bh & 15;
    const int qt = blockIdx.x;

    const float* Qp = g_Q + ((size_t)bh * N_ + qt * 128) * HD_;
    const float* Kp = g_K + (size_t)bh * L_ * HD_;
    const float* Vp = g_V + (size_t)bh * L_ * HD_;
    const unsigned char* mp = g_mask + b * L_;

    // stage Q through smem, then hoist fragments to registers
#pragma unroll
    for (int q = 0; q < 16; q++) {
        int idx = tid + 128 * q;
        int row = idx >> 4, kc = (idx & 15) * 4;
        *(float4*)&Qs[row * SQ + kc] = cvt4(*(const float4*)(Qp + (size_t)row * HD_ + kc));
    }
    __syncthreads();

    const int R = wid * 32;
    uint32_t qreg[8][2][4];   // [ks][mt][frag]
#pragma unroll
    for (int ks = 0; ks < 8; ks++) {
        const int k0 = ks * 8;
#pragma unroll
        for (int mt = 0; mt < 2; mt++) {
            int r = R + mt * 16 + g;
            qreg[ks][mt][0] = __float_as_uint(Qs[r * SQ + k0 + t]);
            qreg[ks][mt][1] = __float_as_uint(Qs[(r + 8) * SQ + k0 + t]);
            qreg[ks][mt][2] = __float_as_uint(Qs[r * SQ + k0 + t + 4]);
            qreg[ks][mt][3] = __float_as_uint(Qs[(r + 8) * SQ + k0 + t + 4]);
        }
    }

    float m[4], l[4];
    float oc[2][8][4];
#pragma unroll
    for (int s = 0; s < 4; s++) { m[s] = MINIT; l[s] = 0.0f; }
#pragma unroll
    for (int mt = 0; mt < 2; mt++)
#pragma unroll
        for (int nt = 0; nt < 8; nt++)
#pragma unroll
            for (int j = 0; j < 4; j++) oc[mt][nt][j] = 0.0f;

    float* Pw = Ps + wid * PWS;

    for (int tt = 0; tt < L_ / 64; tt++) {
        __syncthreads();  // prev iter done reading Ks/Vs/Mb
#pragma unroll
        for (int q = 0; q < 8; q++) {
            int idx = tid + 128 * q;
            int row = idx >> 4, kc = (idx & 15) * 4;
            *(float4*)&Ks[row * SQ + kc] =
                cvt4(*(const float4*)(Kp + (size_t)(tt * 64 + row) * HD_ + kc));
            *(float4*)&Vs[row * SV + kc] =
                cvt4(*(const float4*)(Vp + (size_t)(tt * 64 + row) * HD_ + kc));
        }
        if (tid < 16) {
            uchar4 mv = *(const uchar4*)(mp + tt * 64 + tid * 4);
            Mb[tid * 4 + 0] = mv.x ? MASKBIAS : 0.0f;
            Mb[tid * 4 + 1] = mv.y ? MASKBIAS : 0.0f;
            Mb[tid * 4 + 2] = mv.z ? MASKBIAS : 0.0f;
            Mb[tid * 4 + 3] = mv.w ? MASKBIAS : 0.0f;
        }
        __syncthreads();

        // S = Q K^T  (Q fragments from registers)
        float sc[2][8][4];
#pragma unroll
        for (int mt = 0; mt < 2; mt++)
#pragma unroll
            for (int nt = 0; nt < 8; nt++)
#pragma unroll
                for (int j = 0; j < 4; j++) sc[mt][nt][j] = 0.0f;
#pragma unroll
        for (int ks = 0; ks < 8; ks++) {
            const int k0 = ks * 8;
#pragma unroll
            for (int nt = 0; nt < 8; nt++) {
                int n = nt * 8 + g;
                uint32_t bk[2];
                bk[0] = __float_as_uint(Ks[n * SQ + k0 + t]);
                bk[1] = __float_as_uint(Ks[n * SQ + k0 + t + 4]);
                MMA_TF32(sc[0][nt], qreg[ks][0], bk);
                MMA_TF32(sc[1][nt], qreg[ks][1], bk);
            }
        }

        // mask bias
#pragma unroll
        for (int nt = 0; nt < 8; nt++) {
            float2 mb = *(const float2*)&Mb[nt * 8 + 2 * t];
#pragma unroll
            for (int mt = 0; mt < 2; mt++) {
                sc[mt][nt][0] += mb.x; sc[mt][nt][1] += mb.y;
                sc[mt][nt][2] += mb.x; sc[mt][nt][3] += mb.y;
            }
        }

        // per-row max; rows s = mt*2 + hi
        float tm[4];
#pragma unroll
        for (int s = 0; s < 4; s++) tm[s] = -3.0e38f;
#pragma unroll
        for (int mt = 0; mt < 2; mt++)
#pragma unroll
            for (int nt = 0; nt < 8; nt++) {
                tm[mt * 2 + 0] = fmaxf(tm[mt * 2 + 0], fmaxf(sc[mt][nt][0], sc[mt][nt][1]));
                tm[mt * 2 + 1] = fmaxf(tm[mt * 2 + 1], fmaxf(sc[mt][nt][2], sc[mt][nt][3]));
            }
#pragma unroll
        for (int off = 1; off < 4; off <<= 1)
#pragma unroll
            for (int s = 0; s < 4; s++)
                tm[s] = fmaxf(tm[s], __shfl_xor_sync(0xffffffffu, tm[s], off));

        float al[4], rs[4];
#pragma unroll
        for (int s = 0; s < 4; s++) {
            float mn = fmaxf(m[s], tm[s]);
            al[s] = ex2f(m[s] - mn);
            m[s] = mn;
            rs[s] = 0.0f;
        }
#pragma unroll
        for (int mt = 0; mt < 2; mt++)
#pragma unroll
            for (int nt = 0; nt < 8; nt++) {
                sc[mt][nt][0] = ex2f(sc[mt][nt][0] - m[mt * 2 + 0]);
                sc[mt][nt][1] = ex2f(sc[mt][nt][1] - m[mt * 2 + 0]);
                sc[mt][nt][2] = ex2f(sc[mt][nt][2] - m[mt * 2 + 1]);
                sc[mt][nt][3] = ex2f(sc[mt][nt][3] - m[mt * 2 + 1]);
                rs[mt * 2 + 0] += sc[mt][nt][0] + sc[mt][nt][1];
                rs[mt * 2 + 1] += sc[mt][nt][2] + sc[mt][nt][3];
            }
#pragma unroll
        for (int off = 1; off < 4; off <<= 1)
#pragma unroll
            for (int s = 0; s < 4; s++)
                rs[s] += __shfl_xor_sync(0xffffffffu, rs[s], off);
#pragma unroll
        for (int s = 0; s < 4; s++) l[s] = l[s] * al[s] + rs[s];
#pragma unroll
        for (int mt = 0; mt < 2; mt++)
#pragma unroll
            for (int nt = 0; nt < 8; nt++) {
                oc[mt][nt][0] *= al[mt * 2 + 0]; oc[mt][nt][1] *= al[mt * 2 + 0];
                oc[mt][nt][2] *= al[mt * 2 + 1]; oc[mt][nt][3] *= al[mt * 2 + 1];
            }

        // P store into per-warp buffer (warp-local)
#pragma unroll
        for (int mt = 0; mt < 2; mt++)
#pragma unroll
            for (int nt = 0; nt < 8; nt++) {
                int cc = nt * 8 + 2 * t;
                int lr = mt * 16 + g;
                *(float2*)&Pw[lr * SQ + cc] = make_float2(
                    __uint_as_float(f2tf(sc[mt][nt][0])), __uint_as_float(f2tf(sc[mt][nt][1])));
                *(float2*)&Pw[(lr + 8) * SQ + cc] = make_float2(
                    __uint_as_float(f2tf(sc[mt][nt][2])), __uint_as_float(f2tf(sc[mt][nt][3])));
            }
        __syncwarp();

        // O += P V
#pragma unroll
        for (int ks = 0; ks < 8; ks++) {
            const int k0 = ks * 8;
            uint32_t ap[2][4];
#pragma unroll
            for (int mt = 0; mt < 2; mt++) {
                int lr = mt * 16 + g;
                ap[mt][0] = __float_as_uint(Pw[lr * SQ + k0 + t]);
                ap[mt][1] = __float_as_uint(Pw[(lr + 8) * SQ + k0 + t]);
                ap[mt][2] = __float_as_uint(Pw[lr * SQ + k0 + t + 4]);
                ap[mt][3] = __float_as_uint(Pw[(lr + 8) * SQ + k0 + t + 4]);
            }
#pragma unroll
            for (int nt = 0; nt < 8; nt++) {
                int n = nt * 8 + g;
                uint32_t bv[2];
                bv[0] = __float_as_uint(Vs[(k0 + t) * SV + n]);
                bv[1] = __float_as_uint(Vs[(k0 + t + 4) * SV + n]);
                MMA_TF32(oc[0][nt], ap[0], bv);
                MMA_TF32(oc[1][nt], ap[1], bv);
            }
        }
    }

    // epilogue
    float inv[4];
#pragma unroll
    for (int s = 0; s < 4; s++) inv[s] = 1.0f / l[s];
#pragma unroll
    for (int mt = 0; mt < 2; mt++) {
        int n0r = qt * 128 + R + mt * 16 + g;
        int n1r = n0r + 8;
#pragma unroll
        for (int nt = 0; nt < 8; nt++) {
            int cc = nt * 8 + 2 * t;
            *(float2*)&g_O[((size_t)(b * N_ + n0r)) * D_ + h * HD_ + cc] =
                make_float2(oc[mt][nt][0] * inv[mt * 2 + 0], oc[mt][nt][1] * inv[mt * 2 + 0]);
            *(float2*)&g_O[((size_t)(b * N_ + n1r)) * D_ + h * HD_ + cc] =
                make_float2(oc[mt][nt][2] * inv[mt * 2 + 1], oc[mt][nt][3] * inv[mt * 2 + 1]);
        }
    }
}

// ---------------------------------------------------------------------------
extern "C" void kernel_launch(void* const* d_in, const int* in_sizes, int n_in,
                              void* d_out, int out_size)
{
    (void)in_sizes; (void)n_in; (void)out_size;
    const float* x_q  = (const float*)d_in[0];
    const float* x_kv = (const float*)d_in[1];
    const void*  mraw = d_in[2];
    const float* wq = (const float*)d_in[3];
    const float* bq = (const float*)d_in[4];
    const float* wk = (const float*)d_in[5];
    const float* bk = (const float*)d_in[6];
    const float* wv = (const float*)d_in[7];
    const float* bv = (const float*)d_in[8];
    const float* wo = (const float*)d_in[9];
    const float* bo = (const float*)d_in[10];
    float* out = (float*)d_out;

    static int attr_done = 0;
    if (!attr_done) {
        cudaFuncSetAttribute(proj64<0>, cudaFuncAttributeMaxDynamicSharedMemorySize, PR_SMEM);
        cudaFuncSetAttribute(proj64<1>, cudaFuncAttributeMaxDynamicSharedMemorySize, PR_SMEM);
        cudaFuncSetAttribute(proj64<2>, cudaFuncAttributeMaxDynamicSharedMemorySize, PR_SMEM);
        cudaFuncSetAttribute(proj64<3>, cudaFuncAttributeMaxDynamicSharedMemorySize, PR_SMEM);
        cudaFuncSetAttribute(attn2, cudaFuncAttributeMaxDynamicSharedMemorySize, ATTN_SMEM);
        attr_done = 1;
    }

    mask_prep<<<1, 1024>>>(mraw);

    dim3 gg(D_ / 256, (B_ * N_) / 128);  // (4, 32)
    proj64<0><<<gg, 256, PR_SMEM>>>(x_q, wq, bq, nullptr);
    proj64<1><<<gg, 256, PR_SMEM>>>(x_kv, wk, bk, nullptr);
    proj64<2><<<gg, 256, PR_SMEM>>>(x_kv, wv, bv, nullptr);

    attn2<<<dim3(N_ / 128, B_ * H_), 128, ATTN_SMEM>>>();

    proj64<3><<<gg, 256, PR_SMEM>>>(nullptr, wo, bo, out);
}

// round 9
// speedup vs baseline: 1.5523x; 1.5523x over previous
#include <cuda_runtime.h>
#include <cstdint>

#define B_ 2
#define N_ 2048
#define L_ 2048
#define D_ 1024
#define H_ 16
#define HD_ 64
#define LOG2E 1.4426950408889634f
#define SCALE_Q (0.125f * LOG2E)
#define MASKBIAS (-2.0e30f)
#define MINIT (-1.0e30f)

__device__ float g_Q[(size_t)B_ * H_ * N_ * HD_];
__device__ float g_K[(size_t)B_ * H_ * L_ * HD_];
__device__ float g_V[(size_t)B_ * H_ * L_ * HD_];
__device__ float g_O[(size_t)B_ * N_ * D_];
__device__ unsigned char g_mask[B_ * L_];

__device__ __forceinline__ uint32_t f2tf(float x) {
    uint32_t r; asm("cvt.rna.tf32.f32 %0, %1;" : "=r"(r) : "f"(x)); return r;
}
__device__ __forceinline__ float ex2f(float x) {
    float r; asm("ex2.approx.ftz.f32 %0, %1;" : "=f"(r) : "f"(x)); return r;
}
__device__ __forceinline__ float4 cvt4(float4 v) {
    return make_float4(__uint_as_float(f2tf(v.x)), __uint_as_float(f2tf(v.y)),
                       __uint_as_float(f2tf(v.z)), __uint_as_float(f2tf(v.w)));
}
#define MMA_TF32(C, A, Bf) \
    asm volatile("mma.sync.aligned.m16n8k8.row.col.f32.tf32.tf32.f32 " \
        "{%0,%1,%2,%3},{%4,%5,%6,%7},{%8,%9},{%0,%1,%2,%3};" \
        : "+f"((C)[0]), "+f"((C)[1]), "+f"((C)[2]), "+f"((C)[3]) \
        : "r"((A)[0]), "r"((A)[1]), "r"((A)[2]), "r"((A)[3]), "r"((Bf)[0]), "r"((Bf)[1]))

// ---------------------------------------------------------------------------
__global__ void mask_prep(const void* __restrict__ mraw)
{
    __shared__ int s_isf, s_nb;
    const int t = threadIdx.x;
    if (t == 0) { s_isf = 0; s_nb = 0; }
    __syncthreads();
    const int* ip = (const int*)mraw;
    int v = ip[t];
    if (v == 0x3F800000) atomicExch(&s_isf, 1);
    if (v != 0 && v != 1) atomicExch(&s_nb, 1);
    __syncthreads();
    int mode = s_isf ? 2 : (s_nb ? 1 : 0);
    const unsigned char* bp = (const unsigned char*)mraw;
    const float* fp = (const float*)mraw;
    for (int i = t; i < B_ * L_; i += 1024) {
        unsigned char mv;
        if (mode == 0)      mv = ip[i] != 0;
        else if (mode == 1) mv = bp[i] != 0;
        else                mv = fp[i] != 0.0f;
        g_mask[i] = mv;
    }
}

// ---------------------------------------------------------------------------
// tf32 mma.sync GEMM, warp tile 64x64, BK=32, single-buffered, 2 syncs/stage
// (32 stages). CTA 128(M) x 256(N), 256 threads = 8 warps (2m x 4n).
// MODE 0:Q(*SCALE_Q, head-major) 1:K 2:V 3:out-proj (A = g_O).
// ---------------------------------------------------------------------------
#define SA 36
#define SB 264
#define PR_SMEM ((128 * SA + 32 * SB) * 4)   // 52224 B -> dynamic

template <int MODE>
__global__ void __launch_bounds__(256, 1)
proj64(const float* __restrict__ A, const float* __restrict__ W,
       const float* __restrict__ bias, float* __restrict__ Cout)
{
    extern __shared__ float sm[];
    float* As = sm;                 // 128 x SA
    float* Bs = sm + 128 * SA;      // 32 x SB

    const float* Ap = (MODE == 3) ? (const float*)g_O : A;
    const int tid = threadIdx.x;
    const int lane = tid & 31;
    const int wid = tid >> 5;
    const int g = lane >> 2, t = lane & 3;
    const int wm = wid & 1, wn = wid >> 1;
    const int m0 = blockIdx.y * 128, n0 = blockIdx.x * 256;

    // A: 128 rows x 32 cols / 256 thr = 4 float4 each (rows arow, arow+64; 2 cols)
    const int arow = tid >> 2, akc = (tid & 3) * 8;
    // B: 32 rows x 256 cols / 256 thr = 8 float4 each (rows brow+4q)
    const int brow = tid >> 6, bnc = (tid & 63) * 4;
    const float* aP0 = Ap + (size_t)(m0 + arow) * D_ + akc;
    const float* aP1 = aP0 + (size_t)64 * D_;
    const float* bP = W + (size_t)brow * D_ + n0 + bnc;

    float c[4][8][4];
#pragma unroll
    for (int i = 0; i < 4; i++)
#pragma unroll
        for (int j = 0; j < 8; j++)
#pragma unroll
            for (int k = 0; k < 4; k++) c[i][j][k] = 0.0f;

    float4 ra[4], rb[8];
    ra[0] = *(const float4*)aP0;
    ra[1] = *(const float4*)(aP0 + 4);
    ra[2] = *(const float4*)aP1;
    ra[3] = *(const float4*)(aP1 + 4);
#pragma unroll
    for (int q = 0; q < 8; q++) rb[q] = *(const float4*)(bP + (size_t)(4 * q) * D_);

    for (int kt = 0; kt < 32; kt++) {
        // store tile kt
        *(float4*)&As[arow * SA + akc]            = cvt4(ra[0]);
        *(float4*)&As[arow * SA + akc + 4]        = cvt4(ra[1]);
        *(float4*)&As[(arow + 64) * SA + akc]     = cvt4(ra[2]);
        *(float4*)&As[(arow + 64) * SA + akc + 4] = cvt4(ra[3]);
#pragma unroll
        for (int q = 0; q < 8; q++)
            *(float4*)&Bs[(brow + 4 * q) * SB + bnc] = cvt4(rb[q]);
        __syncthreads();
        // prefetch tile kt+1
        if (kt < 31) {
            size_t oA = (size_t)(kt + 1) * 32;
            ra[0] = *(const float4*)(aP0 + oA);
            ra[1] = *(const float4*)(aP0 + oA + 4);
            ra[2] = *(const float4*)(aP1 + oA);
            ra[3] = *(const float4*)(aP1 + oA + 4);
#pragma unroll
            for (int q = 0; q < 8; q++)
                rb[q] = *(const float4*)(bP + (size_t)((kt + 1) * 32 + 4 * q) * D_);
        }
#pragma unroll
        for (int ks = 0; ks < 4; ks++) {
            const int k0 = ks * 8;
            uint32_t a[4][4];
#pragma unroll
            for (int mt = 0; mt < 4; mt++) {
                int r = wm * 64 + mt * 16 + g;
                a[mt][0] = __float_as_uint(As[r * SA + k0 + t]);
                a[mt][1] = __float_as_uint(As[(r + 8) * SA + k0 + t]);
                a[mt][2] = __float_as_uint(As[r * SA + k0 + t + 4]);
                a[mt][3] = __float_as_uint(As[(r + 8) * SA + k0 + t + 4]);
            }
#pragma unroll
            for (int nt = 0; nt < 8; nt++) {
                int n = wn * 64 + nt * 8 + g;
                uint32_t b[2];
                b[0] = __float_as_uint(Bs[(k0 + t) * SB + n]);
                b[1] = __float_as_uint(Bs[(k0 + t + 4) * SB + n]);
                MMA_TF32(c[0][nt], a[0], b);
                MMA_TF32(c[1][nt], a[1], b);
                MMA_TF32(c[2][nt], a[2], b);
                MMA_TF32(c[3][nt], a[3], b);
            }
        }
        __syncthreads();
    }

    // epilogue
#pragma unroll
    for (int mt = 0; mt < 4; mt++) {
        int r0 = m0 + wm * 64 + mt * 16 + g;
        int r1 = r0 + 8;
#pragma unroll
        for (int nt = 0; nt < 8; nt++) {
            int col = n0 + wn * 64 + nt * 8 + 2 * t;
            float2 bb = *(const float2*)&bias[col];
            float v00 = c[mt][nt][0] + bb.x, v01 = c[mt][nt][1] + bb.y;
            float v10 = c[mt][nt][2] + bb.x, v11 = c[mt][nt][3] + bb.y;
            if (MODE == 0) {
                v00 *= SCALE_Q; v01 *= SCALE_Q; v10 *= SCALE_Q; v11 *= SCALE_Q;
            }
            if (MODE == 3) {
                *(float2*)&Cout[(size_t)r0 * D_ + col] = make_float2(v00, v01);
                *(float2*)&Cout[(size_t)r1 * D_ + col] = make_float2(v10, v11);
            } else {
                float* dst = (MODE == 0) ? g_Q : (MODE == 1) ? g_K : g_V;
                int hh = col >> 6, hd = col & 63;
                {
                    int bb2 = r0 >> 11, n = r0 & 2047;
                    *(float2*)&dst[(((size_t)(bb2 * H_ + hh)) * 2048 + n) * HD_ + hd] =
                        make_float2(v00, v01);
                }
                {
                    int bb2 = r1 >> 11, n = r1 & 2047;
                    *(float2*)&dst[(((size_t)(bb2 * H_ + hh)) * 2048 + n) * HD_ + hd] =
                        make_float2(v10, v11);
                }
            }
        }
    }
}

// ---------------------------------------------------------------------------
// Flash attention: CTA = 128 queries x (b,h); 4 warps, warp tile 32q x 64kv.
// KV tile 64, per-warp private P buffers, 2 block syncs per iteration.
// (exact round-7 version — best measured)
// ---------------------------------------------------------------------------
#define SQ 68
#define SV 72
#define PWS (32 * SQ)
#define ATTN_SMEM ((128 * SQ + 64 * SQ + 64 * SV + 4 * PWS + 64) * 4)

__global__ void __launch_bounds__(128, 2)
attn2()
{
    extern __shared__ float sm[];
    float* Qs = sm;                  // 128*68
    float* Ks = Qs + 128 * SQ;       // 64*68
    float* Vs = Ks + 64 * SQ;        // 64*72
    float* Ps = Vs + 64 * SV;        // 4*32*68
    float* Mb = Ps + 4 * PWS;        // 64

    const int tid = threadIdx.x;
    const int lane = tid & 31, wid = tid >> 5;
    const int g = lane >> 2, t = lane & 3;
    const int bh = blockIdx.y;
    const int b = bh >> 4, h = bh & 15;
    const int qt = blockIdx.x;

    const float* Qp = g_Q + ((size_t)bh * N_ + qt * 128) * HD_;
    const float* Kp = g_K + (size_t)bh * L_ * HD_;
    const float* Vp = g_V + (size_t)bh * L_ * HD_;
    const unsigned char* mp = g_mask + b * L_;

#pragma unroll
    for (int q = 0; q < 16; q++) {
        int idx = tid + 128 * q;
        int row = idx >> 4, kc = (idx & 15) * 4;
        *(float4*)&Qs[row * SQ + kc] = cvt4(*(const float4*)(Qp + (size_t)row * HD_ + kc));
    }

    float m[4], l[4];
    float oc[2][8][4];
#pragma unroll
    for (int s = 0; s < 4; s++) { m[s] = MINIT; l[s] = 0.0f; }
#pragma unroll
    for (int mt = 0; mt < 2; mt++)
#pragma unroll
        for (int nt = 0; nt < 8; nt++)
#pragma unroll
            for (int j = 0; j < 4; j++) oc[mt][nt][j] = 0.0f;

    const int R = wid * 32;
    float* Pw = Ps + wid * PWS;

    for (int tt = 0; tt < L_ / 64; tt++) {
        __syncthreads();
#pragma unroll
        for (int q = 0; q < 8; q++) {
            int idx = tid + 128 * q;
            int row = idx >> 4, kc = (idx & 15) * 4;
            *(float4*)&Ks[row * SQ + kc] =
                cvt4(*(const float4*)(Kp + (size_t)(tt * 64 + row) * HD_ + kc));
            *(float4*)&Vs[row * SV + kc] =
                cvt4(*(const float4*)(Vp + (size_t)(tt * 64 + row) * HD_ + kc));
        }
        if (tid < 16) {
            uchar4 mv = *(const uchar4*)(mp + tt * 64 + tid * 4);
            Mb[tid * 4 + 0] = mv.x ? MASKBIAS : 0.0f;
            Mb[tid * 4 + 1] = mv.y ? MASKBIAS : 0.0f;
            Mb[tid * 4 + 2] = mv.z ? MASKBIAS : 0.0f;
            Mb[tid * 4 + 3] = mv.w ? MASKBIAS : 0.0f;
        }
        __syncthreads();

        float sc[2][8][4];
#pragma unroll
        for (int mt = 0; mt < 2; mt++)
#pragma unroll
            for (int nt = 0; nt < 8; nt++)
#pragma unroll
                for (int j = 0; j < 4; j++) sc[mt][nt][j] = 0.0f;
#pragma unroll
        for (int ks = 0; ks < 8; ks++) {
            const int k0 = ks * 8;
            uint32_t aq[2][4];
#pragma unroll
            for (int mt = 0; mt < 2; mt++) {
                int r = R + mt * 16 + g;
                aq[mt][0] = __float_as_uint(Qs[r * SQ + k0 + t]);
                aq[mt][1] = __float_as_uint(Qs[(r + 8) * SQ + k0 + t]);
                aq[mt][2] = __float_as_uint(Qs[r * SQ + k0 + t + 4]);
                aq[mt][3] = __float_as_uint(Qs[(r + 8) * SQ + k0 + t + 4]);
            }
#pragma unroll
            for (int nt = 0; nt < 8; nt++) {
                int n = nt * 8 + g;
                uint32_t bk[2];
                bk[0] = __float_as_uint(Ks[n * SQ + k0 + t]);
                bk[1] = __float_as_uint(Ks[n * SQ + k0 + t + 4]);
                MMA_TF32(sc[0][nt], aq[0], bk);
                MMA_TF32(sc[1][nt], aq[1], bk);
            }
        }

#pragma unroll
        for (int nt = 0; nt < 8; nt++) {
            float2 mb = *(const float2*)&Mb[nt * 8 + 2 * t];
#pragma unroll
            for (int mt = 0; mt < 2; mt++) {
                sc[mt][nt][0] += mb.x; sc[mt][nt][1] += mb.y;
                sc[mt][nt][2] += mb.x; sc[mt][nt][3] += mb.y;
            }
        }

        float tm[4];
#pragma unroll
        for (int s = 0; s < 4; s++) tm[s] = -3.0e38f;
#pragma unroll
        for (int mt = 0; mt < 2; mt++)
#pragma unroll
            for (int nt = 0; nt < 8; nt++) {
                tm[mt * 2 + 0] = fmaxf(tm[mt * 2 + 0], fmaxf(sc[mt][nt][0], sc[mt][nt][1]));
                tm[mt * 2 + 1] = fmaxf(tm[mt * 2 + 1], fmaxf(sc[mt][nt][2], sc[mt][nt][3]));
            }
#pragma unroll
        for (int off = 1; off < 4; off <<= 1)
#pragma unroll
            for (int s = 0; s < 4; s++)
                tm[s] = fmaxf(tm[s], __shfl_xor_sync(0xffffffffu, tm[s], off));

        float al[4], rs[4];
#pragma unroll
        for (int s = 0; s < 4; s++) {
            float mn = fmaxf(m[s], tm[s]);
            al[s] = ex2f(m[s] - mn);
            m[s] = mn;
            rs[s] = 0.0f;
        }
#pragma unroll
        for (int mt = 0; mt < 2; mt++)
#pragma unroll
            for (int nt = 0; nt < 8; nt++) {
                sc[mt][nt][0] = ex2f(sc[mt][nt][0] - m[mt * 2 + 0]);
                sc[mt][nt][1] = ex2f(sc[mt][nt][1] - m[mt * 2 + 0]);
                sc[mt][nt][2] = ex2f(sc[mt][nt][2] - m[mt * 2 + 1]);
                sc[mt][nt][3] = ex2f(sc[mt][nt][3] - m[mt * 2 + 1]);
                rs[mt * 2 + 0] += sc[mt][nt][0] + sc[mt][nt][1];
                rs[mt * 2 + 1] += sc[mt][nt][2] + sc[mt][nt][3];
            }
#pragma unroll
        for (int off = 1; off < 4; off <<= 1)
#pragma unroll
            for (int s = 0; s < 4; s++)
                rs[s] += __shfl_xor_sync(0xffffffffu, rs[s], off);
#pragma unroll
        for (int s = 0; s < 4; s++) l[s] = l[s] * al[s] + rs[s];
#pragma unroll
        for (int mt = 0; mt < 2; mt++)
#pragma unroll
            for (int nt = 0; nt < 8; nt++) {
                oc[mt][nt][0] *= al[mt * 2 + 0]; oc[mt][nt][1] *= al[mt * 2 + 0];
                oc[mt][nt][2] *= al[mt * 2 + 1]; oc[mt][nt][3] *= al[mt * 2 + 1];
            }

#pragma unroll
        for (int mt = 0; mt < 2; mt++)
#pragma unroll
            for (int nt = 0; nt < 8; nt++) {
                int cc = nt * 8 + 2 * t;
                int lr = mt * 16 + g;
                *(float2*)&Pw[lr * SQ + cc] = make_float2(
                    __uint_as_float(f2tf(sc[mt][nt][0])), __uint_as_float(f2tf(sc[mt][nt][1])));
                *(float2*)&Pw[(lr + 8) * SQ + cc] = make_float2(
                    __uint_as_float(f2tf(sc[mt][nt][2])), __uint_as_float(f2tf(sc[mt][nt][3])));
            }
        __syncwarp();

#pragma unroll
        for (int ks = 0; ks < 8; ks++) {
            const int k0 = ks * 8;
            uint32_t ap[2][4];
#pragma unroll
            for (int mt = 0; mt < 2; mt++) {
                int lr = mt * 16 + g;
                ap[mt][0] = __float_as_uint(Pw[lr * SQ + k0 + t]);
                ap[mt][1] = __float_as_uint(Pw[(lr + 8) * SQ + k0 + t]);
                ap[mt][2] = __float_as_uint(Pw[lr * SQ + k0 + t + 4]);
                ap[mt][3] = __float_as_uint(Pw[(lr + 8) * SQ + k0 + t + 4]);
            }
#pragma unroll
            for (int nt = 0; nt < 8; nt++) {
                int n = nt * 8 + g;
                uint32_t bv[2];
                bv[0] = __float_as_uint(Vs[(k0 + t) * SV + n]);
                bv[1] = __float_as_uint(Vs[(k0 + t + 4) * SV + n]);
                MMA_TF32(oc[0][nt], ap[0], bv);
                MMA_TF32(oc[1][nt], ap[1], bv);
            }
        }
    }

    float inv[4];
#pragma unroll
    for (int s = 0; s < 4; s++) inv[s] = 1.0f / l[s];
#pragma unroll
    for (int mt = 0; mt < 2; mt++) {
        int n0r = qt * 128 + R + mt * 16 + g;
        int n1r = n0r + 8;
#pragma unroll
        for (int nt = 0; nt < 8; nt++) {
            int cc = nt * 8 + 2 * t;
            *(float2*)&g_O[((size_t)(b * N_ + n0r)) * D_ + h * HD_ + cc] =
                make_float2(oc[mt][nt][0] * inv[mt * 2 + 0], oc[mt][nt][1] * inv[mt * 2 + 0]);
            *(float2*)&g_O[((size_t)(b * N_ + n1r)) * D_ + h * HD_ + cc] =
                make_float2(oc[mt][nt][2] * inv[mt * 2 + 1], oc[mt][nt][3] * inv[mt * 2 + 1]);
        }
    }
}

// ---------------------------------------------------------------------------
extern "C" void kernel_launch(void* const* d_in, const int* in_sizes, int n_in,
                              void* d_out, int out_size)
{
    (void)in_sizes; (void)n_in; (void)out_size;
    const float* x_q  = (const float*)d_in[0];
    const float* x_kv = (const float*)d_in[1];
    const void*  mraw = d_in[2];
    const float* wq = (const float*)d_in[3];
    const float* bq = (const float*)d_in[4];
    const float* wk = (const float*)d_in[5];
    const float* bk = (const float*)d_in[6];
    const float* wv = (const float*)d_in[7];
    const float* bv = (const float*)d_in[8];
    const float* wo = (const float*)d_in[9];
    const float* bo = (const float*)d_in[10];
    float* out = (float*)d_out;

    static int attr_done = 0;
    if (!attr_done) {
        cudaFuncSetAttribute(proj64<0>, cudaFuncAttributeMaxDynamicSharedMemorySize, PR_SMEM);
        cudaFuncSetAttribute(proj64<1>, cudaFuncAttributeMaxDynamicSharedMemorySize, PR_SMEM);
        cudaFuncSetAttribute(proj64<2>, cudaFuncAttributeMaxDynamicSharedMemorySize, PR_SMEM);
        cudaFuncSetAttribute(proj64<3>, cudaFuncAttributeMaxDynamicSharedMemorySize, PR_SMEM);
        cudaFuncSetAttribute(attn2, cudaFuncAttributeMaxDynamicSharedMemorySize, ATTN_SMEM);
        attr_done = 1;
    }

    mask_prep<<<1, 1024>>>(mraw);

    dim3 gg(D_ / 256, (B_ * N_) / 128);  // (4, 32)
    proj64<0><<<gg, 256, PR_SMEM>>>(x_q, wq, bq, nullptr);
    proj64<1><<<gg, 256, PR_SMEM>>>(x_kv, wk, bk, nullptr);
    proj64<2><<<gg, 256, PR_SMEM>>>(x_kv, wv, bv, nullptr);

    attn2<<<dim3(N_ / 128, B_ * H_), 128, ATTN_SMEM>>>();

    proj64<3><<<gg, 256, PR_SMEM>>>(nullptr, wo, bo, out);
}

// round 10
// speedup vs baseline: 2.7038x; 1.7418x over previous
#include <cuda_runtime.h>
#include <cuda_fp16.h>
#include <cstdint>

#define B_ 2
#define N_ 2048
#define L_ 2048
#define D_ 1024
#define H_ 16
#define HD_ 64
#define LOG2E 1.4426950408889634f
#define SCALE_Q (0.125f * LOG2E)
#define MASKBIAS (-2.0e30f)
#define MINIT (-1.0e30f)

// half-precision staging buffers (device globals: allocation-free rule)
__device__ __half g_Xq[(size_t)B_ * N_ * D_];
__device__ __half g_Xkv[(size_t)B_ * L_ * D_];
__device__ __half g_WTh[4 * 1024 * 1024];            // [z][n][k]
__device__ __half g_Q[(size_t)B_ * H_ * N_ * HD_];   // [bh][n][hd], *SCALE_Q
__device__ __half g_K[(size_t)B_ * H_ * L_ * HD_];   // [bh][l][hd]
__device__ __half g_V[(size_t)B_ * H_ * L_ * HD_];   // [bh][l][hd]
__device__ __half g_VT[(size_t)B_ * H_ * HD_ * L_];  // [bh][hd][l]
__device__ __half g_O[(size_t)B_ * N_ * D_];         // attention out (B*N, D)
__device__ unsigned char g_mask[B_ * L_];

__device__ __forceinline__ float ex2f(float x) {
    float r; asm("ex2.approx.ftz.f32 %0, %1;" : "=f"(r) : "f"(x)); return r;
}
__device__ __forceinline__ uint32_t h2pack(float lo, float hi) {
    __half2 h = __floats2half2_rn(lo, hi);
    return *(uint32_t*)&h;
}
#define MMA_F16(C, A, Bf) \
    asm volatile("mma.sync.aligned.m16n8k16.row.col.f32.f16.f16.f32 " \
        "{%0,%1,%2,%3},{%4,%5,%6,%7},{%8,%9},{%0,%1,%2,%3};" \
        : "+f"((C)[0]), "+f"((C)[1]), "+f"((C)[2]), "+f"((C)[3]) \
        : "r"((A)[0]), "r"((A)[1]), "r"((A)[2]), "r"((A)[3]), "r"((Bf)[0]), "r"((Bf)[1]))

// ---------------------------------------------------------------------------
__global__ void mask_prep(const void* __restrict__ mraw)
{
    __shared__ int s_isf, s_nb;
    const int t = threadIdx.x;
    if (t == 0) { s_isf = 0; s_nb = 0; }
    __syncthreads();
    const int* ip = (const int*)mraw;
    int v = ip[t];
    if (v == 0x3F800000) atomicExch(&s_isf, 1);
    if (v != 0 && v != 1) atomicExch(&s_nb, 1);
    __syncthreads();
    int mode = s_isf ? 2 : (s_nb ? 1 : 0);
    const unsigned char* bp = (const unsigned char*)mraw;
    const float* fp = (const float*)mraw;
    for (int i = t; i < B_ * L_; i += 1024) {
        unsigned char mv;
        if (mode == 0)      mv = ip[i] != 0;
        else if (mode == 1) mv = bp[i] != 0;
        else                mv = fp[i] != 0.0f;
        g_mask[i] = mv;
    }
}

// x_q, x_kv -> half (4M elems each; 4 per thread)
__global__ void cvt_x(const float* __restrict__ xq, const float* __restrict__ xkv)
{
    int i = blockIdx.x * 256 + threadIdx.x;   // 4096 blocks
    float4 a = ((const float4*)xq)[i];
    float4 b = ((const float4*)xkv)[i];
    __half2* q2 = (__half2*)g_Xq;
    __half2* k2 = (__half2*)g_Xkv;
    q2[2 * i]     = __floats2half2_rn(a.x, a.y);
    q2[2 * i + 1] = __floats2half2_rn(a.z, a.w);
    k2[2 * i]     = __floats2half2_rn(b.x, b.y);
    k2[2 * i + 1] = __floats2half2_rn(b.z, b.w);
}

// W [k][n] fp32 -> g_WTh [z][n][k] half
__global__ void wt_cvt(const float* __restrict__ w0, const float* __restrict__ w1,
                       const float* __restrict__ w2, const float* __restrict__ w3)
{
    __shared__ float t[32][33];
    const float* src = (blockIdx.z == 0) ? w0 : (blockIdx.z == 1) ? w1
                     : (blockIdx.z == 2) ? w2 : w3;
    __half* dst = g_WTh + ((size_t)blockIdx.z << 20);
    int bx = blockIdx.x * 32, by = blockIdx.y * 32;
    int x = threadIdx.x, y0 = threadIdx.y;
#pragma unroll
    for (int i = 0; i < 32; i += 8)
        t[y0 + i][x] = src[(size_t)(by + y0 + i) * 1024 + bx + x];
    __syncthreads();
#pragma unroll
    for (int i = 0; i < 32; i += 8)
        dst[(size_t)(bx + y0 + i) * 1024 + by + x] = __float2half(t[x][y0 + i]);
}

// g_V [bh][kv][d] -> g_VT [bh][d][kv]
__global__ void vtrans()
{
    __shared__ __half t[32][33];
    int bh = blockIdx.z;
    int kv0 = blockIdx.x * 32, d0 = blockIdx.y * 32;
    const __half* src = g_V + (size_t)bh * L_ * HD_;
    __half* dst = g_VT + (size_t)bh * HD_ * L_;
    int x = threadIdx.x, y0 = threadIdx.y;
#pragma unroll
    for (int i = 0; i < 32; i += 8)
        t[y0 + i][x] = src[(size_t)(kv0 + y0 + i) * HD_ + d0 + x];
    __syncthreads();
#pragma unroll
    for (int i = 0; i < 32; i += 8)
        dst[(size_t)(d0 + y0 + i) * L_ + kv0 + x] = t[x][y0 + i];
}

// ---------------------------------------------------------------------------
// fp16 mma.sync GEMM (m16n8k16): C[4096,1024] = A @ W + bias.
// CTA 128x256, BK=32, 8 warps (2m x 4n), warp tile 64x64. All-half hot loop.
// MODE 0:Q(*SCALE_Q, head-major half) 1:K 2:V 3:out-proj (A=g_O, out fp32).
// Smem rows in half2 units, stride 20 (16 + 4 pad): fragment LDS conflict-free.
// ---------------------------------------------------------------------------
#define SA2 20
#define SB2 20

template <int MODE>
__global__ void __launch_bounds__(256, 1)
projh(const float* __restrict__ bias, float* __restrict__ Cout)
{
    __shared__ uint32_t As[128 * SA2];   // [m][k half2]
    __shared__ uint32_t Bs[256 * SB2];   // [n][k half2]

    const __half* Ah = (MODE == 0) ? g_Xq : (MODE == 3) ? g_O : g_Xkv;
    const __half* Wh = g_WTh + ((size_t)MODE << 20);
    const int tid = threadIdx.x;
    const int lane = tid & 31, wid = tid >> 5;
    const int g = lane >> 2, t = lane & 3;
    const int wm = wid & 1, wn = wid >> 1;
    const int m0 = blockIdx.y * 128, n0 = blockIdx.x * 256;

    const int arow = tid >> 2, kc8 = (tid & 3) * 8, kcu = (tid & 3) * 4;
    const __half* aP0 = Ah + (size_t)(m0 + arow) * D_ + kc8;
    const __half* aP1 = aP0 + (size_t)64 * D_;
    const __half* bP = Wh + (size_t)(n0 + arow) * D_ + kc8;   // + 64q rows

    float c[4][8][4];
#pragma unroll
    for (int i = 0; i < 4; i++)
#pragma unroll
        for (int j = 0; j < 8; j++)
#pragma unroll
            for (int k = 0; k < 4; k++) c[i][j][k] = 0.0f;

    uint4 ra[2], rb[4];
    ra[0] = *(const uint4*)aP0;
    ra[1] = *(const uint4*)aP1;
#pragma unroll
    for (int q = 0; q < 4; q++) rb[q] = *(const uint4*)(bP + (size_t)(64 * q) * D_);

    for (int kt = 0; kt < 32; kt++) {
        *(uint4*)&As[arow * SA2 + kcu]        = ra[0];
        *(uint4*)&As[(arow + 64) * SA2 + kcu] = ra[1];
#pragma unroll
        for (int q = 0; q < 4; q++)
            *(uint4*)&Bs[(arow + 64 * q) * SB2 + kcu] = rb[q];
        __syncthreads();
        if (kt < 31) {
            size_t o = (size_t)(kt + 1) * 32;
            ra[0] = *(const uint4*)(aP0 + o);
            ra[1] = *(const uint4*)(aP1 + o);
#pragma unroll
            for (int q = 0; q < 4; q++)
                rb[q] = *(const uint4*)(bP + (size_t)(64 * q) * D_ + o);
        }
#pragma unroll
        for (int kb = 0; kb < 2; kb++) {
            const int k0 = 8 * kb;
            uint32_t a[4][4];
#pragma unroll
            for (int mt = 0; mt < 4; mt++) {
                int r = wm * 64 + mt * 16 + g;
                a[mt][0] = As[r * SA2 + k0 + t];
                a[mt][1] = As[(r + 8) * SA2 + k0 + t];
                a[mt][2] = As[r * SA2 + k0 + t + 4];
                a[mt][3] = As[(r + 8) * SA2 + k0 + t + 4];
            }
#pragma unroll
            for (int nt = 0; nt < 8; nt++) {
                int n = wn * 64 + nt * 8 + g;
                uint32_t b[2];
                b[0] = Bs[n * SB2 + k0 + t];
                b[1] = Bs[n * SB2 + k0 + t + 4];
                MMA_F16(c[0][nt], a[0], b);
                MMA_F16(c[1][nt], a[1], b);
                MMA_F16(c[2][nt], a[2], b);
                MMA_F16(c[3][nt], a[3], b);
            }
        }
        __syncthreads();
    }

    // epilogue
#pragma unroll
    for (int mt = 0; mt < 4; mt++) {
        int r0 = m0 + wm * 64 + mt * 16 + g;
        int r1 = r0 + 8;
#pragma unroll
        for (int nt = 0; nt < 8; nt++) {
            int col = n0 + wn * 64 + nt * 8 + 2 * t;
            float2 bb = *(const float2*)&bias[col];
            float v00 = c[mt][nt][0] + bb.x, v01 = c[mt][nt][1] + bb.y;
            float v10 = c[mt][nt][2] + bb.x, v11 = c[mt][nt][3] + bb.y;
            if (MODE == 0) {
                v00 *= SCALE_Q; v01 *= SCALE_Q; v10 *= SCALE_Q; v11 *= SCALE_Q;
            }
            if (MODE == 3) {
                *(float2*)&Cout[(size_t)r0 * D_ + col] = make_float2(v00, v01);
                *(float2*)&Cout[(size_t)r1 * D_ + col] = make_float2(v10, v11);
            } else {
                __half* dst = (MODE == 0) ? g_Q : (MODE == 1) ? g_K : g_V;
                int hh = col >> 6, hd = col & 63;
                {
                    int bb2 = r0 >> 11, n = r0 & 2047;
                    *(__half2*)(dst + (((size_t)(bb2 * H_ + hh)) * 2048 + n) * HD_ + hd) =
                        __floats2half2_rn(v00, v01);
                }
                {
                    int bb2 = r1 >> 11, n = r1 & 2047;
                    *(__half2*)(dst + (((size_t)(bb2 * H_ + hh)) * 2048 + n) * HD_ + hd) =
                        __floats2half2_rn(v10, v11);
                }
            }
        }
    }
}

// ---------------------------------------------------------------------------
// fp16 flash attention: CTA = 128 queries x (b,h); 4 warps, warp tile 32q x 64kv.
// S via m16n8k16 (Q from smem, K natural layout). P feeds PV DIRECTLY from
// C-fragments (m16n8 C layout == m16n8k16 A layout) — no P smem, no shuffle.
// V pre-transposed globally ([d][kv]) so V B-fragments are contiguous half2.
// smem: Qs[128][36 h2] | Ks[64][36] | Vs[64][36] | Mb[64]  (~37 KB, 2 CTA/SM)
// ---------------------------------------------------------------------------
#define SK2 36

__global__ void __launch_bounds__(128, 2)
attnh()
{
    __shared__ uint32_t Qs[128 * SK2];
    __shared__ uint32_t Ks[64 * SK2];
    __shared__ uint32_t Vs[64 * SK2];
    __shared__ float Mb[64];

    const int tid = threadIdx.x;
    const int lane = tid & 31, wid = tid >> 5;
    const int g = lane >> 2, t = lane & 3;
    const int bh = blockIdx.y;
    const int b = bh >> 4, h = bh & 15;
    const int qt = blockIdx.x;

    const __half* Qp = g_Q + ((size_t)bh * N_ + qt * 128) * HD_;
    const __half* Kp = g_K + (size_t)bh * L_ * HD_;
    const __half* Vtp = g_VT + (size_t)bh * HD_ * L_;
    const unsigned char* mp = g_mask + b * L_;

    // load Q tile (raw half copies)
#pragma unroll
    for (int q = 0; q < 8; q++) {
        int idx = tid + 128 * q;
        int row = idx >> 3, cu = (idx & 7) * 4;
        *(uint4*)&Qs[row * SK2 + cu] = *(const uint4*)(Qp + (size_t)row * HD_ + (idx & 7) * 8);
    }

    float m[4], l[4];
    float oc[2][8][4];
#pragma unroll
    for (int s = 0; s < 4; s++) { m[s] = MINIT; l[s] = 0.0f; }
#pragma unroll
    for (int mt = 0; mt < 2; mt++)
#pragma unroll
        for (int nt = 0; nt < 8; nt++)
#pragma unroll
            for (int j = 0; j < 4; j++) oc[mt][nt][j] = 0.0f;

    const int R = wid * 32;

    for (int tt = 0; tt < L_ / 64; tt++) {
        __syncthreads();  // prev iter done with Ks/Vs/Mb (also orders Q stores @tt=0)
        // K tile [kv][d] natural; V tile from VT [d][kv]
#pragma unroll
        for (int q = 0; q < 4; q++) {
            int idx = tid + 128 * q;
            int row = idx >> 3, c8 = (idx & 7) * 8, cu = (idx & 7) * 4;
            *(uint4*)&Ks[row * SK2 + cu] =
                *(const uint4*)(Kp + (size_t)(tt * 64 + row) * HD_ + c8);
            *(uint4*)&Vs[row * SK2 + cu] =
                *(const uint4*)(Vtp + (size_t)row * L_ + tt * 64 + c8);
        }
        if (tid < 16) {
            uchar4 mv = *(const uchar4*)(mp + tt * 64 + tid * 4);
            Mb[tid * 4 + 0] = mv.x ? MASKBIAS : 0.0f;
            Mb[tid * 4 + 1] = mv.y ? MASKBIAS : 0.0f;
            Mb[tid * 4 + 2] = mv.z ? MASKBIAS : 0.0f;
            Mb[tid * 4 + 3] = mv.w ? MASKBIAS : 0.0f;
        }
        __syncthreads();

        // S = Q K^T  (k = d = 64 -> 4 k16 blocks)
        float sc[2][8][4];
#pragma unroll
        for (int mt = 0; mt < 2; mt++)
#pragma unroll
            for (int nt = 0; nt < 8; nt++)
#pragma unroll
                for (int j = 0; j < 4; j++) sc[mt][nt][j] = 0.0f;
#pragma unroll
        for (int kb = 0; kb < 4; kb++) {
            const int k0 = 8 * kb;
            uint32_t aq[2][4];
#pragma unroll
            for (int mt = 0; mt < 2; mt++) {
                int r = R + mt * 16 + g;
                aq[mt][0] = Qs[r * SK2 + k0 + t];
                aq[mt][1] = Qs[(r + 8) * SK2 + k0 + t];
                aq[mt][2] = Qs[r * SK2 + k0 + t + 4];
                aq[mt][3] = Qs[(r + 8) * SK2 + k0 + t + 4];
            }
#pragma unroll
            for (int nt = 0; nt < 8; nt++) {
                int n = nt * 8 + g;
                uint32_t bk[2];
                bk[0] = Ks[n * SK2 + k0 + t];
                bk[1] = Ks[n * SK2 + k0 + t + 4];
                MMA_F16(sc[0][nt], aq[0], bk);
                MMA_F16(sc[1][nt], aq[1], bk);
            }
        }

        // mask bias
#pragma unroll
        for (int nt = 0; nt < 8; nt++) {
            float2 mb = *(const float2*)&Mb[nt * 8 + 2 * t];
#pragma unroll
            for (int mt = 0; mt < 2; mt++) {
                sc[mt][nt][0] += mb.x; sc[mt][nt][1] += mb.y;
                sc[mt][nt][2] += mb.x; sc[mt][nt][3] += mb.y;
            }
        }

        // online softmax (rows s = mt*2 + hi; quad reduction)
        float tm[4];
#pragma unroll
        for (int s = 0; s < 4; s++) tm[s] = -3.0e38f;
#pragma unroll
        for (int mt = 0; mt < 2; mt++)
#pragma unroll
            for (int nt = 0; nt < 8; nt++) {
                tm[mt * 2 + 0] = fmaxf(tm[mt * 2 + 0], fmaxf(sc[mt][nt][0], sc[mt][nt][1]));
                tm[mt * 2 + 1] = fmaxf(tm[mt * 2 + 1], fmaxf(sc[mt][nt][2], sc[mt][nt][3]));
            }
#pragma unroll
        for (int off = 1; off < 4; off <<= 1)
#pragma unroll
            for (int s = 0; s < 4; s++)
                tm[s] = fmaxf(tm[s], __shfl_xor_sync(0xffffffffu, tm[s], off));

        float al[4], rs[4];
#pragma unroll
        for (int s = 0; s < 4; s++) {
            float mn = fmaxf(m[s], tm[s]);
            al[s] = ex2f(m[s] - mn);
            m[s] = mn;
            rs[s] = 0.0f;
        }
#pragma unroll
        for (int mt = 0; mt < 2; mt++)
#pragma unroll
            for (int nt = 0; nt < 8; nt++) {
                sc[mt][nt][0] = ex2f(sc[mt][nt][0] - m[mt * 2 + 0]);
                sc[mt][nt][1] = ex2f(sc[mt][nt][1] - m[mt * 2 + 0]);
                sc[mt][nt][2] = ex2f(sc[mt][nt][2] - m[mt * 2 + 1]);
                sc[mt][nt][3] = ex2f(sc[mt][nt][3] - m[mt * 2 + 1]);
                rs[mt * 2 + 0] += sc[mt][nt][0] + sc[mt][nt][1];
                rs[mt * 2 + 1] += sc[mt][nt][2] + sc[mt][nt][3];
            }
#pragma unroll
        for (int off = 1; off < 4; off <<= 1)
#pragma unroll
            for (int s = 0; s < 4; s++)
                rs[s] += __shfl_xor_sync(0xffffffffu, rs[s], off);
#pragma unroll
        for (int s = 0; s < 4; s++) l[s] = l[s] * al[s] + rs[s];
#pragma unroll
        for (int mt = 0; mt < 2; mt++)
#pragma unroll
            for (int nt = 0; nt < 8; nt++) {
                oc[mt][nt][0] *= al[mt * 2 + 0]; oc[mt][nt][1] *= al[mt * 2 + 0];
                oc[mt][nt][2] *= al[mt * 2 + 1]; oc[mt][nt][3] *= al[mt * 2 + 1];
            }

        // O += P V : P direct from C-fragments (k16 block j = nt blocks 2j, 2j+1)
#pragma unroll
        for (int j = 0; j < 4; j++) {
            const int k0 = 8 * j;
            uint32_t ap[2][4];
#pragma unroll
            for (int mt = 0; mt < 2; mt++) {
                ap[mt][0] = h2pack(sc[mt][2 * j][0], sc[mt][2 * j][1]);
                ap[mt][1] = h2pack(sc[mt][2 * j][2], sc[mt][2 * j][3]);
                ap[mt][2] = h2pack(sc[mt][2 * j + 1][0], sc[mt][2 * j + 1][1]);
                ap[mt][3] = h2pack(sc[mt][2 * j + 1][2], sc[mt][2 * j + 1][3]);
            }
#pragma unroll
            for (int nt = 0; nt < 8; nt++) {
                int n = nt * 8 + g;
                uint32_t bv[2];
                bv[0] = Vs[n * SK2 + k0 + t];
                bv[1] = Vs[n * SK2 + k0 + t + 4];
                MMA_F16(oc[0][nt], ap[0], bv);
                MMA_F16(oc[1][nt], ap[1], bv);
            }
        }
    }

    // epilogue: normalize, write half into g_O head-major
    float inv[4];
#pragma unroll
    for (int s = 0; s < 4; s++) inv[s] = 1.0f / l[s];
#pragma unroll
    for (int mt = 0; mt < 2; mt++) {
        int n0r = qt * 128 + R + mt * 16 + g;
        int n1r = n0r + 8;
#pragma unroll
        for (int nt = 0; nt < 8; nt++) {
            int cc = nt * 8 + 2 * t;
            *(__half2*)(g_O + ((size_t)(b * N_ + n0r)) * D_ + h * HD_ + cc) =
                __floats2half2_rn(oc[mt][nt][0] * inv[mt * 2 + 0],
                                  oc[mt][nt][1] * inv[mt * 2 + 0]);
            *(__half2*)(g_O + ((size_t)(b * N_ + n1r)) * D_ + h * HD_ + cc) =
                __floats2half2_rn(oc[mt][nt][2] * inv[mt * 2 + 1],
                                  oc[mt][nt][3] * inv[mt * 2 + 1]);
        }
    }
}

// ---------------------------------------------------------------------------
extern "C" void kernel_launch(void* const* d_in, const int* in_sizes, int n_in,
                              void* d_out, int out_size)
{
    (void)in_sizes; (void)n_in; (void)out_size;
    const float* x_q  = (const float*)d_in[0];
    const float* x_kv = (const float*)d_in[1];
    const void*  mraw = d_in[2];
    const float* wq = (const float*)d_in[3];
    const float* bq = (const float*)d_in[4];
    const float* wk = (const float*)d_in[5];
    const float* bk = (const float*)d_in[6];
    const float* wv = (const float*)d_in[7];
    const float* bv = (const float*)d_in[8];
    const float* wo = (const float*)d_in[9];
    const float* bo = (const float*)d_in[10];
    float* out = (float*)d_out;

    mask_prep<<<1, 1024>>>(mraw);
    cvt_x<<<4096, 256>>>(x_q, x_kv);
    wt_cvt<<<dim3(32, 32, 4), dim3(32, 8)>>>(wq, wk, wv, wo);

    dim3 gg(D_ / 256, (B_ * N_) / 128);  // (4, 32)
    projh<0><<<gg, 256>>>(bq, nullptr);
    projh<1><<<gg, 256>>>(bk, nullptr);
    projh<2><<<gg, 256>>>(bv, nullptr);

    vtrans<<<dim3(64, 2, 32), dim3(32, 8)>>>();

    attnh<<<dim3(N_ / 128, B_ * H_), 128>>>();

    projh<3><<<gg, 256>>>(bo, out);
}

// round 11
// speedup vs baseline: 2.8072x; 1.0383x over previous
#include <cuda_runtime.h>
#include <cuda_fp16.h>
#include <cstdint>

#define B_ 2
#define N_ 2048
#define L_ 2048
#define D_ 1024
#define H_ 16
#define HD_ 64
#define LOG2E 1.4426950408889634f
#define SCALE_Q (0.125f * LOG2E)
#define MASKBIAS (-2.0e30f)
#define MINIT (-1.0e30f)

__device__ __half g_Xq[(size_t)B_ * N_ * D_];
__device__ __half g_Xkv[(size_t)B_ * L_ * D_];
__device__ __half g_WTh[4 * 1024 * 1024];            // [z][n][k]
__device__ __half g_Q[(size_t)B_ * H_ * N_ * HD_];   // *SCALE_Q
__device__ __half g_K[(size_t)B_ * H_ * L_ * HD_];
__device__ __half g_V[(size_t)B_ * H_ * L_ * HD_];
__device__ __half g_VT[(size_t)B_ * H_ * HD_ * L_];  // [bh][d][l]
__device__ __half g_O[(size_t)B_ * N_ * D_];
__device__ unsigned char g_mask[B_ * L_];

__device__ __forceinline__ float ex2f(float x) {
    float r; asm("ex2.approx.ftz.f32 %0, %1;" : "=f"(r) : "f"(x)); return r;
}
__device__ __forceinline__ uint32_t h2pack(float lo, float hi) {
    __half2 h = __floats2half2_rn(lo, hi);
    return *(uint32_t*)&h;
}
__device__ __forceinline__ uint32_t smem_u32(const void* p) {
    uint32_t a;
    asm("{ .reg .u64 t; cvta.to.shared.u64 t, %1; cvt.u32.u64 %0, t; }" : "=r"(a) : "l"(p));
    return a;
}
__device__ __forceinline__ void cpa16(uint32_t dst, const void* src) {
    asm volatile("cp.async.cg.shared.global [%0], [%1], 16;" :: "r"(dst), "l"(src));
}
#define CPA_COMMIT() asm volatile("cp.async.commit_group;" ::: "memory")
#define CPA_WAIT0()  asm volatile("cp.async.wait_group 0;" ::: "memory")

#define MMA_F16(C, A, Bf) \
    asm volatile("mma.sync.aligned.m16n8k16.row.col.f32.f16.f16.f32 " \
        "{%0,%1,%2,%3},{%4,%5,%6,%7},{%8,%9},{%0,%1,%2,%3};" \
        : "+f"((C)[0]), "+f"((C)[1]), "+f"((C)[2]), "+f"((C)[3]) \
        : "r"((A)[0]), "r"((A)[1]), "r"((A)[2]), "r"((A)[3]), "r"((Bf)[0]), "r"((Bf)[1]))

// ---------------------------------------------------------------------------
__global__ void mask_prep(const void* __restrict__ mraw)
{
    __shared__ int s_isf, s_nb;
    const int t = threadIdx.x;
    if (t == 0) { s_isf = 0; s_nb = 0; }
    __syncthreads();
    const int* ip = (const int*)mraw;
    int v = ip[t];
    if (v == 0x3F800000) atomicExch(&s_isf, 1);
    if (v != 0 && v != 1) atomicExch(&s_nb, 1);
    __syncthreads();
    int mode = s_isf ? 2 : (s_nb ? 1 : 0);
    const unsigned char* bp = (const unsigned char*)mraw;
    const float* fp = (const float*)mraw;
    for (int i = t; i < B_ * L_; i += 1024) {
        unsigned char mv;
        if (mode == 0)      mv = ip[i] != 0;
        else if (mode == 1) mv = bp[i] != 0;
        else                mv = fp[i] != 0.0f;
        g_mask[i] = mv;
    }
}

__global__ void cvt_x(const float* __restrict__ xq, const float* __restrict__ xkv)
{
    int i = blockIdx.x * 256 + threadIdx.x;
    float4 a = ((const float4*)xq)[i];
    float4 b = ((const float4*)xkv)[i];
    __half2* q2 = (__half2*)g_Xq;
    __half2* k2 = (__half2*)g_Xkv;
    q2[2 * i]     = __floats2half2_rn(a.x, a.y);
    q2[2 * i + 1] = __floats2half2_rn(a.z, a.w);
    k2[2 * i]     = __floats2half2_rn(b.x, b.y);
    k2[2 * i + 1] = __floats2half2_rn(b.z, b.w);
}

__global__ void wt_cvt(const float* __restrict__ w0, const float* __restrict__ w1,
                       const float* __restrict__ w2, const float* __restrict__ w3)
{
    __shared__ float t[32][33];
    const float* src = (blockIdx.z == 0) ? w0 : (blockIdx.z == 1) ? w1
                     : (blockIdx.z == 2) ? w2 : w3;
    __half* dst = g_WTh + ((size_t)blockIdx.z << 20);
    int bx = blockIdx.x * 32, by = blockIdx.y * 32;
    int x = threadIdx.x, y0 = threadIdx.y;
#pragma unroll
    for (int i = 0; i < 32; i += 8)
        t[y0 + i][x] = src[(size_t)(by + y0 + i) * 1024 + bx + x];
    __syncthreads();
#pragma unroll
    for (int i = 0; i < 32; i += 8)
        dst[(size_t)(bx + y0 + i) * 1024 + by + x] = __float2half(t[x][y0 + i]);
}

__global__ void vtrans()
{
    __shared__ __half t[32][33];
    int bh = blockIdx.z;
    int kv0 = blockIdx.x * 32, d0 = blockIdx.y * 32;
    const __half* src = g_V + (size_t)bh * L_ * HD_;
    __half* dst = g_VT + (size_t)bh * HD_ * L_;
    int x = threadIdx.x, y0 = threadIdx.y;
#pragma unroll
    for (int i = 0; i < 32; i += 8)
        t[y0 + i][x] = src[(size_t)(kv0 + y0 + i) * HD_ + d0 + x];
    __syncthreads();
#pragma unroll
    for (int i = 0; i < 32; i += 8)
        dst[(size_t)(d0 + y0 + i) * L_ + kv0 + x] = t[x][y0 + i];
}

// ---------------------------------------------------------------------------
// fp16 GEMM, cp.async double-buffered, BK=64, 1 sync/stage (16 stages).
// CTA 128x256, 8 warps (2m x 4n), warp tile 64x64. Runtime mode:
// 0:Q(*SCALE_Q) 1:K 2:V (grid.z selects) 3:out-proj (fp32 out).
// smem uint32 stride 36/row: [A0][A1][B0][B1] = 110592 B.
// ---------------------------------------------------------------------------
#define SP2 36
#define AB_SZ (128 * SP2)
#define BB_SZ (256 * SP2)
#define PR_SMEM ((2 * AB_SZ + 2 * BB_SZ) * 4)

__global__ void __launch_bounds__(256, 1)
projp(int mode_base, const float* __restrict__ b0, const float* __restrict__ b1,
      const float* __restrict__ b2, const float* __restrict__ b3,
      float* __restrict__ Cout)
{
    extern __shared__ uint32_t smp[];
    const uint32_t sbase = smem_u32(smp);
    const int mode = mode_base + blockIdx.z;

    const __half* Ah = (mode == 0) ? g_Xq : (mode == 3) ? g_O : g_Xkv;
    const __half* Wh = g_WTh + ((size_t)mode << 20);
    const float* bias = (mode == 0) ? b0 : (mode == 1) ? b1 : (mode == 2) ? b2 : b3;

    const int tid = threadIdx.x;
    const int lane = tid & 31, wid = tid >> 5;
    const int g = lane >> 2, t = lane & 3;
    const int wm = wid & 1, wn = wid >> 1;
    const int m0 = blockIdx.y * 128, n0 = blockIdx.x * 256;

    // cp.async chunk mapping (16B = 8 halves = 4 uint32)
    const int crow = tid >> 3, cc = tid & 7;   // base row/col-chunk

    float c[4][8][4];
#pragma unroll
    for (int i = 0; i < 4; i++)
#pragma unroll
        for (int j = 0; j < 8; j++)
#pragma unroll
            for (int k = 0; k < 4; k++) c[i][j][k] = 0.0f;

    // issue stage 0 into buf 0
    {
        const int stage = 0, buf = 0;
        const uint32_t aoff = buf * AB_SZ, boff = 2 * AB_SZ + buf * BB_SZ;
#pragma unroll
        for (int q = 0; q < 4; q++) {   // A: 128 rows
            int row = crow + 32 * q;
            cpa16(sbase + (aoff + row * SP2 + cc * 4) * 4,
                  Ah + (size_t)(m0 + row) * D_ + stage * 64 + cc * 8);
        }
#pragma unroll
        for (int q = 0; q < 8; q++) {   // B: 256 rows
            int row = crow + 32 * q;
            cpa16(sbase + (boff + row * SP2 + cc * 4) * 4,
                  Wh + (size_t)(n0 + row) * D_ + stage * 64 + cc * 8);
        }
        CPA_COMMIT();
    }

    for (int kt = 0; kt < 16; kt++) {
        CPA_WAIT0();
        __syncthreads();
        if (kt < 15) {
            const int buf = (kt + 1) & 1;
            const uint32_t aoff = buf * AB_SZ, boff = 2 * AB_SZ + buf * BB_SZ;
#pragma unroll
            for (int q = 0; q < 4; q++) {
                int row = crow + 32 * q;
                cpa16(sbase + (aoff + row * SP2 + cc * 4) * 4,
                      Ah + (size_t)(m0 + row) * D_ + (kt + 1) * 64 + cc * 8);
            }
#pragma unroll
            for (int q = 0; q < 8; q++) {
                int row = crow + 32 * q;
                cpa16(sbase + (boff + row * SP2 + cc * 4) * 4,
                      Wh + (size_t)(n0 + row) * D_ + (kt + 1) * 64 + cc * 8);
            }
            CPA_COMMIT();
        }
        const uint32_t* As = smp + (kt & 1) * AB_SZ;
        const uint32_t* Bs = smp + 2 * AB_SZ + (kt & 1) * BB_SZ;
#pragma unroll
        for (int kb = 0; kb < 4; kb++) {
            const int k0 = 8 * kb;
            uint32_t a[4][4];
#pragma unroll
            for (int mt = 0; mt < 4; mt++) {
                int r = wm * 64 + mt * 16 + g;
                a[mt][0] = As[r * SP2 + k0 + t];
                a[mt][1] = As[(r + 8) * SP2 + k0 + t];
                a[mt][2] = As[r * SP2 + k0 + t + 4];
                a[mt][3] = As[(r + 8) * SP2 + k0 + t + 4];
            }
#pragma unroll
            for (int nt = 0; nt < 8; nt++) {
                int n = wn * 64 + nt * 8 + g;
                uint32_t b[2];
                b[0] = Bs[n * SP2 + k0 + t];
                b[1] = Bs[n * SP2 + k0 + t + 4];
                MMA_F16(c[0][nt], a[0], b);
                MMA_F16(c[1][nt], a[1], b);
                MMA_F16(c[2][nt], a[2], b);
                MMA_F16(c[3][nt], a[3], b);
            }
        }
    }

    // epilogue
#pragma unroll
    for (int mt = 0; mt < 4; mt++) {
        int r0 = m0 + wm * 64 + mt * 16 + g;
        int r1 = r0 + 8;
#pragma unroll
        for (int nt = 0; nt < 8; nt++) {
            int col = n0 + wn * 64 + nt * 8 + 2 * t;
            float2 bb = *(const float2*)&bias[col];
            float v00 = c[mt][nt][0] + bb.x, v01 = c[mt][nt][1] + bb.y;
            float v10 = c[mt][nt][2] + bb.x, v11 = c[mt][nt][3] + bb.y;
            if (mode == 0) {
                v00 *= SCALE_Q; v01 *= SCALE_Q; v10 *= SCALE_Q; v11 *= SCALE_Q;
            }
            if (mode == 3) {
                *(float2*)&Cout[(size_t)r0 * D_ + col] = make_float2(v00, v01);
                *(float2*)&Cout[(size_t)r1 * D_ + col] = make_float2(v10, v11);
            } else {
                __half* dst = (mode == 0) ? g_Q : (mode == 1) ? g_K : g_V;
                int hh = col >> 6, hd = col & 63;
                {
                    int bb2 = r0 >> 11, n = r0 & 2047;
                    *(__half2*)(dst + (((size_t)(bb2 * H_ + hh)) * 2048 + n) * HD_ + hd) =
                        __floats2half2_rn(v00, v01);
                }
                {
                    int bb2 = r1 >> 11, n = r1 & 2047;
                    *(__half2*)(dst + (((size_t)(bb2 * H_ + hh)) * 2048 + n) * HD_ + hd) =
                        __floats2half2_rn(v10, v11);
                }
            }
        }
    }
}

// ---------------------------------------------------------------------------
// fp16 flash attention (unchanged from round 10 — 287 TF/s).
// ---------------------------------------------------------------------------
#define SK2 36

__global__ void __launch_bounds__(128, 2)
attnh()
{
    __shared__ uint32_t Qs[128 * SK2];
    __shared__ uint32_t Ks[64 * SK2];
    __shared__ uint32_t Vs[64 * SK2];
    __shared__ float Mb[64];

    const int tid = threadIdx.x;
    const int lane = tid & 31, wid = tid >> 5;
    const int g = lane >> 2, t = lane & 3;
    const int bh = blockIdx.y;
    const int b = bh >> 4, h = bh & 15;
    const int qt = blockIdx.x;

    const __half* Qp = g_Q + ((size_t)bh * N_ + qt * 128) * HD_;
    const __half* Kp = g_K + (size_t)bh * L_ * HD_;
    const __half* Vtp = g_VT + (size_t)bh * HD_ * L_;
    const unsigned char* mp = g_mask + b * L_;

#pragma unroll
    for (int q = 0; q < 8; q++) {
        int idx = tid + 128 * q;
        int row = idx >> 3, cu = (idx & 7) * 4;
        *(uint4*)&Qs[row * SK2 + cu] = *(const uint4*)(Qp + (size_t)row * HD_ + (idx & 7) * 8);
    }

    float m[4], l[4];
    float oc[2][8][4];
#pragma unroll
    for (int s = 0; s < 4; s++) { m[s] = MINIT; l[s] = 0.0f; }
#pragma unroll
    for (int mt = 0; mt < 2; mt++)
#pragma unroll
        for (int nt = 0; nt < 8; nt++)
#pragma unroll
            for (int j = 0; j < 4; j++) oc[mt][nt][j] = 0.0f;

    const int R = wid * 32;

    for (int tt = 0; tt < L_ / 64; tt++) {
        __syncthreads();
#pragma unroll
        for (int q = 0; q < 4; q++) {
            int idx = tid + 128 * q;
            int row = idx >> 3, c8 = (idx & 7) * 8, cu = (idx & 7) * 4;
            *(uint4*)&Ks[row * SK2 + cu] =
                *(const uint4*)(Kp + (size_t)(tt * 64 + row) * HD_ + c8);
            *(uint4*)&Vs[row * SK2 + cu] =
                *(const uint4*)(Vtp + (size_t)row * L_ + tt * 64 + c8);
        }
        if (tid < 16) {
            uchar4 mv = *(const uchar4*)(mp + tt * 64 + tid * 4);
            Mb[tid * 4 + 0] = mv.x ? MASKBIAS : 0.0f;
            Mb[tid * 4 + 1] = mv.y ? MASKBIAS : 0.0f;
            Mb[tid * 4 + 2] = mv.z ? MASKBIAS : 0.0f;
            Mb[tid * 4 + 3] = mv.w ? MASKBIAS : 0.0f;
        }
        __syncthreads();

        float sc[2][8][4];
#pragma unroll
        for (int mt = 0; mt < 2; mt++)
#pragma unroll
            for (int nt = 0; nt < 8; nt++)
#pragma unroll
                for (int j = 0; j < 4; j++) sc[mt][nt][j] = 0.0f;
#pragma unroll
        for (int kb = 0; kb < 4; kb++) {
            const int k0 = 8 * kb;
            uint32_t aq[2][4];
#pragma unroll
            for (int mt = 0; mt < 2; mt++) {
                int r = R + mt * 16 + g;
                aq[mt][0] = Qs[r * SK2 + k0 + t];
                aq[mt][1] = Qs[(r + 8) * SK2 + k0 + t];
                aq[mt][2] = Qs[r * SK2 + k0 + t + 4];
                aq[mt][3] = Qs[(r + 8) * SK2 + k0 + t + 4];
            }
#pragma unroll
            for (int nt = 0; nt < 8; nt++) {
                int n = nt * 8 + g;
                uint32_t bk[2];
                bk[0] = Ks[n * SK2 + k0 + t];
                bk[1] = Ks[n * SK2 + k0 + t + 4];
                MMA_F16(sc[0][nt], aq[0], bk);
                MMA_F16(sc[1][nt], aq[1], bk);
            }
        }

#pragma unroll
        for (int nt = 0; nt < 8; nt++) {
            float2 mb = *(const float2*)&Mb[nt * 8 + 2 * t];
#pragma unroll
            for (int mt = 0; mt < 2; mt++) {
                sc[mt][nt][0] += mb.x; sc[mt][nt][1] += mb.y;
                sc[mt][nt][2] += mb.x; sc[mt][nt][3] += mb.y;
            }
        }

        float tm[4];
#pragma unroll
        for (int s = 0; s < 4; s++) tm[s] = -3.0e38f;
#pragma unroll
        for (int mt = 0; mt < 2; mt++)
#pragma unroll
            for (int nt = 0; nt < 8; nt++) {
                tm[mt * 2 + 0] = fmaxf(tm[mt * 2 + 0], fmaxf(sc[mt][nt][0], sc[mt][nt][1]));
                tm[mt * 2 + 1] = fmaxf(tm[mt * 2 + 1], fmaxf(sc[mt][nt][2], sc[mt][nt][3]));
            }
#pragma unroll
        for (int off = 1; off < 4; off <<= 1)
#pragma unroll
            for (int s = 0; s < 4; s++)
                tm[s] = fmaxf(tm[s], __shfl_xor_sync(0xffffffffu, tm[s], off));

        float al[4], rs[4];
#pragma unroll
        for (int s = 0; s < 4; s++) {
            float mn = fmaxf(m[s], tm[s]);
            al[s] = ex2f(m[s] - mn);
            m[s] = mn;
            rs[s] = 0.0f;
        }
#pragma unroll
        for (int mt = 0; mt < 2; mt++)
#pragma unroll
            for (int nt = 0; nt < 8; nt++) {
                sc[mt][nt][0] = ex2f(sc[mt][nt][0] - m[mt * 2 + 0]);
                sc[mt][nt][1] = ex2f(sc[mt][nt][1] - m[mt * 2 + 0]);
                sc[mt][nt][2] = ex2f(sc[mt][nt][2] - m[mt * 2 + 1]);
                sc[mt][nt][3] = ex2f(sc[mt][nt][3] - m[mt * 2 + 1]);
                rs[mt * 2 + 0] += sc[mt][nt][0] + sc[mt][nt][1];
                rs[mt * 2 + 1] += sc[mt][nt][2] + sc[mt][nt][3];
            }
#pragma unroll
        for (int off = 1; off < 4; off <<= 1)
#pragma unroll
            for (int s = 0; s < 4; s++)
                rs[s] += __shfl_xor_sync(0xffffffffu, rs[s], off);
#pragma unroll
        for (int s = 0; s < 4; s++) l[s] = l[s] * al[s] + rs[s];
#pragma unroll
        for (int mt = 0; mt < 2; mt++)
#pragma unroll
            for (int nt = 0; nt < 8; nt++) {
                oc[mt][nt][0] *= al[mt * 2 + 0]; oc[mt][nt][1] *= al[mt * 2 + 0];
                oc[mt][nt][2] *= al[mt * 2 + 1]; oc[mt][nt][3] *= al[mt * 2 + 1];
            }

#pragma unroll
        for (int j = 0; j < 4; j++) {
            const int k0 = 8 * j;
            uint32_t ap[2][4];
#pragma unroll
            for (int mt = 0; mt < 2; mt++) {
                ap[mt][0] = h2pack(sc[mt][2 * j][0], sc[mt][2 * j][1]);
                ap[mt][1] = h2pack(sc[mt][2 * j][2], sc[mt][2 * j][3]);
                ap[mt][2] = h2pack(sc[mt][2 * j + 1][0], sc[mt][2 * j + 1][1]);
                ap[mt][3] = h2pack(sc[mt][2 * j + 1][2], sc[mt][2 * j + 1][3]);
            }
#pragma unroll
            for (int nt = 0; nt < 8; nt++) {
                int n = nt * 8 + g;
                uint32_t bv[2];
                bv[0] = Vs[n * SK2 + k0 + t];
                bv[1] = Vs[n * SK2 + k0 + t + 4];
                MMA_F16(oc[0][nt], ap[0], bv);
                MMA_F16(oc[1][nt], ap[1], bv);
            }
        }
    }

    float inv[4];
#pragma unroll
    for (int s = 0; s < 4; s++) inv[s] = 1.0f / l[s];
#pragma unroll
    for (int mt = 0; mt < 2; mt++) {
        int n0r = qt * 128 + R + mt * 16 + g;
        int n1r = n0r + 8;
#pragma unroll
        for (int nt = 0; nt < 8; nt++) {
            int cc = nt * 8 + 2 * t;
            *(__half2*)(g_O + ((size_t)(b * N_ + n0r)) * D_ + h * HD_ + cc) =
                __floats2half2_rn(oc[mt][nt][0] * inv[mt * 2 + 0],
                                  oc[mt][nt][1] * inv[mt * 2 + 0]);
            *(__half2*)(g_O + ((size_t)(b * N_ + n1r)) * D_ + h * HD_ + cc) =
                __floats2half2_rn(oc[mt][nt][2] * inv[mt * 2 + 1],
                                  oc[mt][nt][3] * inv[mt * 2 + 1]);
        }
    }
}

// ---------------------------------------------------------------------------
extern "C" void kernel_launch(void* const* d_in, const int* in_sizes, int n_in,
                              void* d_out, int out_size)
{
    (void)in_sizes; (void)n_in; (void)out_size;
    const float* x_q  = (const float*)d_in[0];
    const float* x_kv = (const float*)d_in[1];
    const void*  mraw = d_in[2];
    const float* wq = (const float*)d_in[3];
    const float* bq = (const float*)d_in[4];
    const float* wk = (const float*)d_in[5];
    const float* bk = (const float*)d_in[6];
    const float* wv = (const float*)d_in[7];
    const float* bv = (const float*)d_in[8];
    const float* wo = (const float*)d_in[9];
    const float* bo = (const float*)d_in[10];
    float* out = (float*)d_out;

    static int attr_done = 0;
    if (!attr_done) {
        cudaFuncSetAttribute(projp, cudaFuncAttributeMaxDynamicSharedMemorySize, PR_SMEM);
        attr_done = 1;
    }

    mask_prep<<<1, 1024>>>(mraw);
    cvt_x<<<4096, 256>>>(x_q, x_kv);
    wt_cvt<<<dim3(32, 32, 4), dim3(32, 8)>>>(wq, wk, wv, wo);

    projp<<<dim3(4, 32, 3), 256, PR_SMEM>>>(0, bq, bk, bv, bo, nullptr);

    vtrans<<<dim3(64, 2, 32), dim3(32, 8)>>>();

    attnh<<<dim3(N_ / 128, B_ * H_), 128>>>();

    projp<<<dim3(4, 32, 1), 256, PR_SMEM>>>(3, bq, bk, bv, bo, out);
}

// round 12
// speedup vs baseline: 2.9708x; 1.0583x over previous
#include <cuda_runtime.h>
#include <cuda_fp16.h>
#include <cstdint>

#define B_ 2
#define N_ 2048
#define L_ 2048
#define D_ 1024
#define H_ 16
#define HD_ 64
#define LOG2E 1.4426950408889634f
#define SCALE_Q (0.125f * LOG2E)
#define MASKBIAS (-2.0e30f)
#define MINIT (-1.0e30f)

__device__ __half g_Xq[(size_t)B_ * N_ * D_];
__device__ __half g_Xkv[(size_t)B_ * L_ * D_];
__device__ __half g_WTh[4 * 1024 * 1024];            // [z][n][k]
__device__ __half g_Q[(size_t)B_ * H_ * N_ * HD_];   // *SCALE_Q
__device__ __half g_K[(size_t)B_ * H_ * L_ * HD_];
__device__ __half g_V[(size_t)B_ * H_ * L_ * HD_];
__device__ __half g_VT[(size_t)B_ * H_ * HD_ * L_];  // [bh][d][l]
__device__ __half g_O[(size_t)B_ * N_ * D_];
__device__ unsigned char g_mask[B_ * L_];

__device__ __forceinline__ float ex2f(float x) {
    float r; asm("ex2.approx.ftz.f32 %0, %1;" : "=f"(r) : "f"(x)); return r;
}
__device__ __forceinline__ uint32_t h2pack(float lo, float hi) {
    __half2 h = __floats2half2_rn(lo, hi);
    return *(uint32_t*)&h;
}
__device__ __forceinline__ uint32_t smem_u32(const void* p) {
    uint32_t a;
    asm("{ .reg .u64 t; cvta.to.shared.u64 t, %1; cvt.u32.u64 %0, t; }" : "=r"(a) : "l"(p));
    return a;
}
__device__ __forceinline__ void cpa16(uint32_t dst, const void* src) {
    asm volatile("cp.async.cg.shared.global [%0], [%1], 16;" :: "r"(dst), "l"(src));
}
#define CPA_COMMIT() asm volatile("cp.async.commit_group;" ::: "memory")
#define CPA_WAIT0()  asm volatile("cp.async.wait_group 0;" ::: "memory")
#define CPA_WAIT1()  asm volatile("cp.async.wait_group 1;" ::: "memory")

#define MMA_F16(C, A, Bf) \
    asm volatile("mma.sync.aligned.m16n8k16.row.col.f32.f16.f16.f32 " \
        "{%0,%1,%2,%3},{%4,%5,%6,%7},{%8,%9},{%0,%1,%2,%3};" \
        : "+f"((C)[0]), "+f"((C)[1]), "+f"((C)[2]), "+f"((C)[3]) \
        : "r"((A)[0]), "r"((A)[1]), "r"((A)[2]), "r"((A)[3]), "r"((Bf)[0]), "r"((Bf)[1]))

// ---------------------------------------------------------------------------
__global__ void mask_prep(const void* __restrict__ mraw)
{
    __shared__ int s_isf, s_nb;
    const int t = threadIdx.x;
    if (t == 0) { s_isf = 0; s_nb = 0; }
    __syncthreads();
    const int* ip = (const int*)mraw;
    int v = ip[t];
    if (v == 0x3F800000) atomicExch(&s_isf, 1);
    if (v != 0 && v != 1) atomicExch(&s_nb, 1);
    __syncthreads();
    int mode = s_isf ? 2 : (s_nb ? 1 : 0);
    const unsigned char* bp = (const unsigned char*)mraw;
    const float* fp = (const float*)mraw;
    for (int i = t; i < B_ * L_; i += 1024) {
        unsigned char mv;
        if (mode == 0)      mv = ip[i] != 0;
        else if (mode == 1) mv = bp[i] != 0;
        else                mv = fp[i] != 0.0f;
        g_mask[i] = mv;
    }
}

__global__ void cvt_x(const float* __restrict__ xq, const float* __restrict__ xkv)
{
    int i = blockIdx.x * 256 + threadIdx.x;
    float4 a = ((const float4*)xq)[i];
    float4 b = ((const float4*)xkv)[i];
    __half2* q2 = (__half2*)g_Xq;
    __half2* k2 = (__half2*)g_Xkv;
    q2[2 * i]     = __floats2half2_rn(a.x, a.y);
    q2[2 * i + 1] = __floats2half2_rn(a.z, a.w);
    k2[2 * i]     = __floats2half2_rn(b.x, b.y);
    k2[2 * i + 1] = __floats2half2_rn(b.z, b.w);
}

__global__ void wt_cvt(const float* __restrict__ w0, const float* __restrict__ w1,
                       const float* __restrict__ w2, const float* __restrict__ w3)
{
    __shared__ float t[32][33];
    const float* src = (blockIdx.z == 0) ? w0 : (blockIdx.z == 1) ? w1
                     : (blockIdx.z == 2) ? w2 : w3;
    __half* dst = g_WTh + ((size_t)blockIdx.z << 20);
    int bx = blockIdx.x * 32, by = blockIdx.y * 32;
    int x = threadIdx.x, y0 = threadIdx.y;
#pragma unroll
    for (int i = 0; i < 32; i += 8)
        t[y0 + i][x] = src[(size_t)(by + y0 + i) * 1024 + bx + x];
    __syncthreads();
#pragma unroll
    for (int i = 0; i < 32; i += 8)
        dst[(size_t)(bx + y0 + i) * 1024 + by + x] = __float2half(t[x][y0 + i]);
}

__global__ void vtrans()
{
    __shared__ __half t[32][33];
    int bh = blockIdx.z;
    int kv0 = blockIdx.x * 32, d0 = blockIdx.y * 32;
    const __half* src = g_V + (size_t)bh * L_ * HD_;
    __half* dst = g_VT + (size_t)bh * HD_ * L_;
    int x = threadIdx.x, y0 = threadIdx.y;
#pragma unroll
    for (int i = 0; i < 32; i += 8)
        t[y0 + i][x] = src[(size_t)(kv0 + y0 + i) * HD_ + d0 + x];
    __syncthreads();
#pragma unroll
    for (int i = 0; i < 32; i += 8)
        dst[(size_t)(d0 + y0 + i) * L_ + kv0 + x] = t[x][y0 + i];
}

// ---------------------------------------------------------------------------
// fp16 GEMM, 3-stage cp.async pipeline, BK=64, 1 sync/stage (16 stages).
// CTA 128x256, 8 warps (2m x 4n), warp tile 64x64. Runtime mode:
// 0:Q(*SCALE_Q) 1:K 2:V (grid.z) 3:out-proj (fp32 out).
// smem u32: A[3][128*36] then B[3][256*36] = 165888 B.
// ---------------------------------------------------------------------------
#define SP2 36
#define AB_SZ (128 * SP2)
#define BB_SZ (256 * SP2)
#define PR_SMEM ((3 * AB_SZ + 3 * BB_SZ) * 4)

__global__ void __launch_bounds__(256, 1)
projp(int mode_base, const float* __restrict__ b0, const float* __restrict__ b1,
      const float* __restrict__ b2, const float* __restrict__ b3,
      float* __restrict__ Cout)
{
    extern __shared__ uint32_t smp[];
    const uint32_t sbase = smem_u32(smp);
    const int mode = mode_base + blockIdx.z;

    const __half* Ah = (mode == 0) ? g_Xq : (mode == 3) ? g_O : g_Xkv;
    const __half* Wh = g_WTh + ((size_t)mode << 20);
    const float* bias = (mode == 0) ? b0 : (mode == 1) ? b1 : (mode == 2) ? b2 : b3;

    const int tid = threadIdx.x;
    const int lane = tid & 31, wid = tid >> 5;
    const int g = lane >> 2, t = lane & 3;
    const int wm = wid & 1, wn = wid >> 1;
    const int m0 = blockIdx.y * 128, n0 = blockIdx.x * 256;

    const int crow = tid >> 3, cc = tid & 7;   // cp.async chunk mapping

    float c[4][8][4];
#pragma unroll
    for (int i = 0; i < 4; i++)
#pragma unroll
        for (int j = 0; j < 8; j++)
#pragma unroll
            for (int k = 0; k < 4; k++) c[i][j][k] = 0.0f;

    // issue a stage into buffer s
    auto issue = [&](int stage, int s) {
        const uint32_t aoff = s * AB_SZ, boff = 3 * AB_SZ + s * BB_SZ;
#pragma unroll
        for (int q = 0; q < 4; q++) {
            int row = crow + 32 * q;
            cpa16(sbase + (aoff + row * SP2 + cc * 4) * 4,
                  Ah + (size_t)(m0 + row) * D_ + stage * 64 + cc * 8);
        }
#pragma unroll
        for (int q = 0; q < 8; q++) {
            int row = crow + 32 * q;
            cpa16(sbase + (boff + row * SP2 + cc * 4) * 4,
                  Wh + (size_t)(n0 + row) * D_ + stage * 64 + cc * 8);
        }
    };

    issue(0, 0); CPA_COMMIT();
    issue(1, 1); CPA_COMMIT();

    int rbuf = 0, wbuf = 2;
    for (int kt = 0; kt < 16; kt++) {
        CPA_WAIT1();          // stage kt landed (<=1 group outstanding)
        __syncthreads();
        if (kt + 2 < 16) issue(kt + 2, wbuf);
        CPA_COMMIT();         // always commit (tail drains via empty groups)
        const uint32_t* As = smp + rbuf * AB_SZ;
        const uint32_t* Bs = smp + 3 * AB_SZ + rbuf * BB_SZ;
#pragma unroll
        for (int kb = 0; kb < 4; kb++) {
            const int k0 = 8 * kb;
            uint32_t a[4][4];
#pragma unroll
            for (int mt = 0; mt < 4; mt++) {
                int r = wm * 64 + mt * 16 + g;
                a[mt][0] = As[r * SP2 + k0 + t];
                a[mt][1] = As[(r + 8) * SP2 + k0 + t];
                a[mt][2] = As[r * SP2 + k0 + t + 4];
                a[mt][3] = As[(r + 8) * SP2 + k0 + t + 4];
            }
#pragma unroll
            for (int nt = 0; nt < 8; nt++) {
                int n = wn * 64 + nt * 8 + g;
                uint32_t b[2];
                b[0] = Bs[n * SP2 + k0 + t];
                b[1] = Bs[n * SP2 + k0 + t + 4];
                MMA_F16(c[0][nt], a[0], b);
                MMA_F16(c[1][nt], a[1], b);
                MMA_F16(c[2][nt], a[2], b);
                MMA_F16(c[3][nt], a[3], b);
            }
        }
        rbuf = (rbuf == 2) ? 0 : rbuf + 1;
        wbuf = (wbuf == 2) ? 0 : wbuf + 1;
    }

    // epilogue
#pragma unroll
    for (int mt = 0; mt < 4; mt++) {
        int r0 = m0 + wm * 64 + mt * 16 + g;
        int r1 = r0 + 8;
#pragma unroll
        for (int nt = 0; nt < 8; nt++) {
            int col = n0 + wn * 64 + nt * 8 + 2 * t;
            float2 bb = *(const float2*)&bias[col];
            float v00 = c[mt][nt][0] + bb.x, v01 = c[mt][nt][1] + bb.y;
            float v10 = c[mt][nt][2] + bb.x, v11 = c[mt][nt][3] + bb.y;
            if (mode == 0) {
                v00 *= SCALE_Q; v01 *= SCALE_Q; v10 *= SCALE_Q; v11 *= SCALE_Q;
            }
            if (mode == 3) {
                *(float2*)&Cout[(size_t)r0 * D_ + col] = make_float2(v00, v01);
                *(float2*)&Cout[(size_t)r1 * D_ + col] = make_float2(v10, v11);
            } else {
                __half* dst = (mode == 0) ? g_Q : (mode == 1) ? g_K : g_V;
                int hh = col >> 6, hd = col & 63;
                {
                    int bb2 = r0 >> 11, n = r0 & 2047;
                    *(__half2*)(dst + (((size_t)(bb2 * H_ + hh)) * 2048 + n) * HD_ + hd) =
                        __floats2half2_rn(v00, v01);
                }
                {
                    int bb2 = r1 >> 11, n = r1 & 2047;
                    *(__half2*)(dst + (((size_t)(bb2 * H_ + hh)) * 2048 + n) * HD_ + hd) =
                        __floats2half2_rn(v10, v11);
                }
            }
        }
    }
}

// ---------------------------------------------------------------------------
// fp16 flash attention, cp.async double-buffered K/V, 1 sync per iteration.
// CTA = 128q x (b,h), 4 warps (32q x 64kv each). P from C-fragments.
// dyn smem u32: Qs[128*36] | Ks[2][64*36] | Vs[2][64*36] | Mb[2][64] f32
// ---------------------------------------------------------------------------
#define SK2 36
#define QS_SZ (128 * SK2)
#define KV_SZ (64 * SK2)
#define ATTN_SMEM ((QS_SZ + 4 * KV_SZ) * 4 + 2 * 64 * 4)

__global__ void __launch_bounds__(128, 2)
attnh()
{
    extern __shared__ uint32_t smA[];
    uint32_t* Qs = smA;                       // 128*36
    uint32_t* Ksb = smA + QS_SZ;              // 2 x 64*36
    uint32_t* Vsb = smA + QS_SZ + 2 * KV_SZ;  // 2 x 64*36
    float* Mbb = (float*)(smA + QS_SZ + 4 * KV_SZ);  // 2 x 64
    const uint32_t sbase = smem_u32(smA);

    const int tid = threadIdx.x;
    const int lane = tid & 31, wid = tid >> 5;
    const int g = lane >> 2, t = lane & 3;
    const int bh = blockIdx.y;
    const int b = bh >> 4, h = bh & 15;
    const int qt = blockIdx.x;

    const __half* Qp = g_Q + ((size_t)bh * N_ + qt * 128) * HD_;
    const __half* Kp = g_K + (size_t)bh * L_ * HD_;
    const __half* Vtp = g_VT + (size_t)bh * HD_ * L_;
    const unsigned char* mp = g_mask + b * L_;

    // Q tile (plain copies)
#pragma unroll
    for (int q = 0; q < 8; q++) {
        int idx = tid + 128 * q;
        int row = idx >> 3, cu = (idx & 7) * 4;
        *(uint4*)&Qs[row * SK2 + cu] = *(const uint4*)(Qp + (size_t)row * HD_ + (idx & 7) * 8);
    }

    // cp.async issue of K/V tile tt into buffer s
    auto issue_kv = [&](int tt, int s) {
#pragma unroll
        for (int q = 0; q < 4; q++) {
            int idx = tid + 128 * q;
            int row = idx >> 3, ch = idx & 7;
            cpa16(sbase + (QS_SZ + s * KV_SZ + row * SK2 + ch * 4) * 4,
                  Kp + (size_t)(tt * 64 + row) * HD_ + ch * 8);
            cpa16(sbase + (QS_SZ + 2 * KV_SZ + s * KV_SZ + row * SK2 + ch * 4) * 4,
                  Vtp + (size_t)row * L_ + tt * 64 + ch * 8);
        }
    };
    auto load_mb = [&](int tt, int s) {
        if (tid < 16) {
            uchar4 mv = *(const uchar4*)(mp + tt * 64 + tid * 4);
            float* Mb = Mbb + s * 64;
            Mb[tid * 4 + 0] = mv.x ? MASKBIAS : 0.0f;
            Mb[tid * 4 + 1] = mv.y ? MASKBIAS : 0.0f;
            Mb[tid * 4 + 2] = mv.z ? MASKBIAS : 0.0f;
            Mb[tid * 4 + 3] = mv.w ? MASKBIAS : 0.0f;
        }
    };

    issue_kv(0, 0); CPA_COMMIT();
    load_mb(0, 0);

    float m[4], l[4];
    float oc[2][8][4];
#pragma unroll
    for (int s = 0; s < 4; s++) { m[s] = MINIT; l[s] = 0.0f; }
#pragma unroll
    for (int mt = 0; mt < 2; mt++)
#pragma unroll
        for (int nt = 0; nt < 8; nt++)
#pragma unroll
            for (int j = 0; j < 4; j++) oc[mt][nt][j] = 0.0f;

    const int R = wid * 32;
    const int NT = L_ / 64;

    for (int tt = 0; tt < NT; tt++) {
        const int cb = tt & 1;
        CPA_WAIT0();          // tile tt landed
        __syncthreads();      // all warps past compute(tt-1); data visible
        if (tt + 1 < NT) issue_kv(tt + 1, cb ^ 1);
        CPA_COMMIT();
        if (tt + 1 < NT) load_mb(tt + 1, cb ^ 1);

        const uint32_t* Ks = Ksb + cb * KV_SZ;
        const uint32_t* Vs = Vsb + cb * KV_SZ;
        const float* Mb = Mbb + cb * 64;

        // S = Q K^T
        float sc[2][8][4];
#pragma unroll
        for (int mt = 0; mt < 2; mt++)
#pragma unroll
            for (int nt = 0; nt < 8; nt++)
#pragma unroll
                for (int j = 0; j < 4; j++) sc[mt][nt][j] = 0.0f;
#pragma unroll
        for (int kb = 0; kb < 4; kb++) {
            const int k0 = 8 * kb;
            uint32_t aq[2][4];
#pragma unroll
            for (int mt = 0; mt < 2; mt++) {
                int r = R + mt * 16 + g;
                aq[mt][0] = Qs[r * SK2 + k0 + t];
                aq[mt][1] = Qs[(r + 8) * SK2 + k0 + t];
                aq[mt][2] = Qs[r * SK2 + k0 + t + 4];
                aq[mt][3] = Qs[(r + 8) * SK2 + k0 + t + 4];
            }
#pragma unroll
            for (int nt = 0; nt < 8; nt++) {
                int n = nt * 8 + g;
                uint32_t bk[2];
                bk[0] = Ks[n * SK2 + k0 + t];
                bk[1] = Ks[n * SK2 + k0 + t + 4];
                MMA_F16(sc[0][nt], aq[0], bk);
                MMA_F16(sc[1][nt], aq[1], bk);
            }
        }

        // mask bias
#pragma unroll
        for (int nt = 0; nt < 8; nt++) {
            float2 mb = *(const float2*)&Mb[nt * 8 + 2 * t];
#pragma unroll
            for (int mt = 0; mt < 2; mt++) {
                sc[mt][nt][0] += mb.x; sc[mt][nt][1] += mb.y;
                sc[mt][nt][2] += mb.x; sc[mt][nt][3] += mb.y;
            }
        }

        // online softmax
        float tm[4];
#pragma unroll
        for (int s = 0; s < 4; s++) tm[s] = -3.0e38f;
#pragma unroll
        for (int mt = 0; mt < 2; mt++)
#pragma unroll
            for (int nt = 0; nt < 8; nt++) {
                tm[mt * 2 + 0] = fmaxf(tm[mt * 2 + 0], fmaxf(sc[mt][nt][0], sc[mt][nt][1]));
                tm[mt * 2 + 1] = fmaxf(tm[mt * 2 + 1], fmaxf(sc[mt][nt][2], sc[mt][nt][3]));
            }
#pragma unroll
        for (int off = 1; off < 4; off <<= 1)
#pragma unroll
            for (int s = 0; s < 4; s++)
                tm[s] = fmaxf(tm[s], __shfl_xor_sync(0xffffffffu, tm[s], off));

        float al[4], rs[4];
#pragma unroll
        for (int s = 0; s < 4; s++) {
            float mn = fmaxf(m[s], tm[s]);
            al[s] = ex2f(m[s] - mn);
            m[s] = mn;
            rs[s] = 0.0f;
        }
#pragma unroll
        for (int mt = 0; mt < 2; mt++)
#pragma unroll
            for (int nt = 0; nt < 8; nt++) {
                sc[mt][nt][0] = ex2f(sc[mt][nt][0] - m[mt * 2 + 0]);
                sc[mt][nt][1] = ex2f(sc[mt][nt][1] - m[mt * 2 + 0]);
                sc[mt][nt][2] = ex2f(sc[mt][nt][2] - m[mt * 2 + 1]);
                sc[mt][nt][3] = ex2f(sc[mt][nt][3] - m[mt * 2 + 1]);
                rs[mt * 2 + 0] += sc[mt][nt][0] + sc[mt][nt][1];
                rs[mt * 2 + 1] += sc[mt][nt][2] + sc[mt][nt][3];
            }
#pragma unroll
        for (int off = 1; off < 4; off <<= 1)
#pragma unroll
            for (int s = 0; s < 4; s++)
                rs[s] += __shfl_xor_sync(0xffffffffu, rs[s], off);
#pragma unroll
        for (int s = 0; s < 4; s++) l[s] = l[s] * al[s] + rs[s];
#pragma unroll
        for (int mt = 0; mt < 2; mt++)
#pragma unroll
            for (int nt = 0; nt < 8; nt++) {
                oc[mt][nt][0] *= al[mt * 2 + 0]; oc[mt][nt][1] *= al[mt * 2 + 0];
                oc[mt][nt][2] *= al[mt * 2 + 1]; oc[mt][nt][3] *= al[mt * 2 + 1];
            }

        // O += P V (P direct from C-fragments)
#pragma unroll
        for (int j = 0; j < 4; j++) {
            const int k0 = 8 * j;
            uint32_t ap[2][4];
#pragma unroll
            for (int mt = 0; mt < 2; mt++) {
                ap[mt][0] = h2pack(sc[mt][2 * j][0], sc[mt][2 * j][1]);
                ap[mt][1] = h2pack(sc[mt][2 * j][2], sc[mt][2 * j][3]);
                ap[mt][2] = h2pack(sc[mt][2 * j + 1][0], sc[mt][2 * j + 1][1]);
                ap[mt][3] = h2pack(sc[mt][2 * j + 1][2], sc[mt][2 * j + 1][3]);
            }
#pragma unroll
            for (int nt = 0; nt < 8; nt++) {
                int n = nt * 8 + g;
                uint32_t bv[2];
                bv[0] = Vs[n * SK2 + k0 + t];
                bv[1] = Vs[n * SK2 + k0 + t + 4];
                MMA_F16(oc[0][nt], ap[0], bv);
                MMA_F16(oc[1][nt], ap[1], bv);
            }
        }
    }

    float inv[4];
#pragma unroll
    for (int s = 0; s < 4; s++) inv[s] = 1.0f / l[s];
#pragma unroll
    for (int mt = 0; mt < 2; mt++) {
        int n0r = qt * 128 + R + mt * 16 + g;
        int n1r = n0r + 8;
#pragma unroll
        for (int nt = 0; nt < 8; nt++) {
            int cc = nt * 8 + 2 * t;
            *(__half2*)(g_O + ((size_t)(b * N_ + n0r)) * D_ + h * HD_ + cc) =
                __floats2half2_rn(oc[mt][nt][0] * inv[mt * 2 + 0],
                                  oc[mt][nt][1] * inv[mt * 2 + 0]);
            *(__half2*)(g_O + ((size_t)(b * N_ + n1r)) * D_ + h * HD_ + cc) =
                __floats2half2_rn(oc[mt][nt][2] * inv[mt * 2 + 1],
                                  oc[mt][nt][3] * inv[mt * 2 + 1]);
        }
    }
}

// ---------------------------------------------------------------------------
extern "C" void kernel_launch(void* const* d_in, const int* in_sizes, int n_in,
                              void* d_out, int out_size)
{
    (void)in_sizes; (void)n_in; (void)out_size;
    const float* x_q  = (const float*)d_in[0];
    const float* x_kv = (const float*)d_in[1];
    const void*  mraw = d_in[2];
    const float* wq = (const float*)d_in[3];
    const float* bq = (const float*)d_in[4];
    const float* wk = (const float*)d_in[5];
    const float* bk = (const float*)d_in[6];
    const float* wv = (const float*)d_in[7];
    const float* bv = (const float*)d_in[8];
    const float* wo = (const float*)d_in[9];
    const float* bo = (const float*)d_in[10];
    float* out = (float*)d_out;

    static int attr_done = 0;
    if (!attr_done) {
        cudaFuncSetAttribute(projp, cudaFuncAttributeMaxDynamicSharedMemorySize, PR_SMEM);
        cudaFuncSetAttribute(attnh, cudaFuncAttributeMaxDynamicSharedMemorySize, ATTN_SMEM);
        attr_done = 1;
    }

    mask_prep<<<1, 1024>>>(mraw);
    cvt_x<<<4096, 256>>>(x_q, x_kv);
    wt_cvt<<<dim3(32, 32, 4), dim3(32, 8)>>>(wq, wk, wv, wo);

    projp<<<dim3(4, 32, 3), 256, PR_SMEM>>>(0, bq, bk, bv, bo, nullptr);

    vtrans<<<dim3(64, 2, 32), dim3(32, 8)>>>();

    attnh<<<dim3(N_ / 128, B_ * H_), 128, ATTN_SMEM>>>();

    projp<<<dim3(4, 32, 1), 256, PR_SMEM>>>(3, bq, bk, bv, bo, out);
}

// round 13
// speedup vs baseline: 3.0285x; 1.0194x over previous
#include <cuda_runtime.h>
#include <cuda_fp16.h>
#include <cstdint>

#define B_ 2
#define N_ 2048
#define L_ 2048
#define D_ 1024
#define H_ 16
#define HD_ 64
#define LOG2E 1.4426950408889634f
#define SCALE_Q (0.125f * LOG2E)
#define MASKBIAS (-2.0e30f)
#define MINIT (-1.0e30f)

__device__ __half g_Xq[(size_t)B_ * N_ * D_];
__device__ __half g_Xkv[(size_t)B_ * L_ * D_];
__device__ __half g_WTh[4 * 1024 * 1024];            // [z][n][k]
__device__ __half g_Q[(size_t)B_ * H_ * N_ * HD_];   // *SCALE_Q
__device__ __half g_K[(size_t)B_ * H_ * L_ * HD_];
__device__ __half g_V[(size_t)B_ * H_ * L_ * HD_];
__device__ __half g_VT[(size_t)B_ * H_ * HD_ * L_];  // [bh][d][l]
__device__ __half g_O[(size_t)B_ * N_ * D_];
__device__ unsigned char g_mask[B_ * L_];

__device__ __forceinline__ float ex2f(float x) {
    float r; asm("ex2.approx.ftz.f32 %0, %1;" : "=f"(r) : "f"(x)); return r;
}
__device__ __forceinline__ uint32_t h2pack(float lo, float hi) {
    __half2 h = __floats2half2_rn(lo, hi);
    return *(uint32_t*)&h;
}
__device__ __forceinline__ uint32_t smem_u32(const void* p) {
    uint32_t a;
    asm("{ .reg .u64 t; cvta.to.shared.u64 t, %1; cvt.u32.u64 %0, t; }" : "=r"(a) : "l"(p));
    return a;
}
__device__ __forceinline__ void cpa16(uint32_t dst, const void* src) {
    asm volatile("cp.async.cg.shared.global [%0], [%1], 16;" :: "r"(dst), "l"(src));
}
#define CPA_COMMIT() asm volatile("cp.async.commit_group;" ::: "memory")
#define CPA_WAIT0()  asm volatile("cp.async.wait_group 0;" ::: "memory")

#define MMA_F16(C, A, Bf) \
    asm volatile("mma.sync.aligned.m16n8k16.row.col.f32.f16.f16.f32 " \
        "{%0,%1,%2,%3},{%4,%5,%6,%7},{%8,%9},{%0,%1,%2,%3};" \
        : "+f"((C)[0]), "+f"((C)[1]), "+f"((C)[2]), "+f"((C)[3]) \
        : "r"((A)[0]), "r"((A)[1]), "r"((A)[2]), "r"((A)[3]), "r"((Bf)[0]), "r"((Bf)[1]))

// ---------------------------------------------------------------------------
__global__ void mask_prep(const void* __restrict__ mraw)
{
    __shared__ int s_isf, s_nb;
    const int t = threadIdx.x;
    if (t == 0) { s_isf = 0; s_nb = 0; }
    __syncthreads();
    const int* ip = (const int*)mraw;
    int v = ip[t];
    if (v == 0x3F800000) atomicExch(&s_isf, 1);
    if (v != 0 && v != 1) atomicExch(&s_nb, 1);
    __syncthreads();
    int mode = s_isf ? 2 : (s_nb ? 1 : 0);
    const unsigned char* bp = (const unsigned char*)mraw;
    const float* fp = (const float*)mraw;
    for (int i = t; i < B_ * L_; i += 1024) {
        unsigned char mv;
        if (mode == 0)      mv = ip[i] != 0;
        else if (mode == 1) mv = bp[i] != 0;
        else                mv = fp[i] != 0.0f;
        g_mask[i] = mv;
    }
}

__global__ void cvt_x(const float* __restrict__ xq, const float* __restrict__ xkv)
{
    int i = blockIdx.x * 256 + threadIdx.x;
    float4 a = ((const float4*)xq)[i];
    float4 b = ((const float4*)xkv)[i];
    __half2* q2 = (__half2*)g_Xq;
    __half2* k2 = (__half2*)g_Xkv;
    q2[2 * i]     = __floats2half2_rn(a.x, a.y);
    q2[2 * i + 1] = __floats2half2_rn(a.z, a.w);
    k2[2 * i]     = __floats2half2_rn(b.x, b.y);
    k2[2 * i + 1] = __floats2half2_rn(b.z, b.w);
}

__global__ void wt_cvt(const float* __restrict__ w0, const float* __restrict__ w1,
                       const float* __restrict__ w2, const float* __restrict__ w3)
{
    __shared__ float t[32][33];
    const float* src = (blockIdx.z == 0) ? w0 : (blockIdx.z == 1) ? w1
                     : (blockIdx.z == 2) ? w2 : w3;
    __half* dst = g_WTh + ((size_t)blockIdx.z << 20);
    int bx = blockIdx.x * 32, by = blockIdx.y * 32;
    int x = threadIdx.x, y0 = threadIdx.y;
#pragma unroll
    for (int i = 0; i < 32; i += 8)
        t[y0 + i][x] = src[(size_t)(by + y0 + i) * 1024 + bx + x];
    __syncthreads();
#pragma unroll
    for (int i = 0; i < 32; i += 8)
        dst[(size_t)(bx + y0 + i) * 1024 + by + x] = __float2half(t[x][y0 + i]);
}

__global__ void vtrans()
{
    __shared__ __half t[32][33];
    int bh = blockIdx.z;
    int kv0 = blockIdx.x * 32, d0 = blockIdx.y * 32;
    const __half* src = g_V + (size_t)bh * L_ * HD_;
    __half* dst = g_VT + (size_t)bh * HD_ * L_;
    int x = threadIdx.x, y0 = threadIdx.y;
#pragma unroll
    for (int i = 0; i < 32; i += 8)
        t[y0 + i][x] = src[(size_t)(kv0 + y0 + i) * HD_ + d0 + x];
    __syncthreads();
#pragma unroll
    for (int i = 0; i < 32; i += 8)
        dst[(size_t)(d0 + y0 + i) * L_ + kv0 + x] = t[x][y0 + i];
}

// ---------------------------------------------------------------------------
// fp16 GEMM, cp.async double-buffered, BK=64, CTA 128x128 with 4 warps
// (warp tile 64x64, 2x2), launch_bounds(128,2) -> 2 CTAs/SM so two CTAs
// interleave: one CTA's barrier/load phase hides behind the other's MMAs
// (the configuration that makes the attention kernel 2.4x faster per SM).
// Runtime mode: 0:Q(*SCALE_Q) 1:K 2:V (grid.z) 3:out-proj (fp32 out).
// smem u32: [A0][A1][B0][B1], each 128*36 -> 73728 B/CTA.
// ---------------------------------------------------------------------------
#define SP2 36
#define TB_SZ (128 * SP2)
#define PR_SMEM (4 * TB_SZ * 4)

__global__ void __launch_bounds__(128, 2)
projp(int mode_base, const float* __restrict__ b0, const float* __restrict__ b1,
      const float* __restrict__ b2, const float* __restrict__ b3,
      float* __restrict__ Cout)
{
    extern __shared__ uint32_t smp[];
    const uint32_t sbase = smem_u32(smp);
    const int mode = mode_base + blockIdx.z;

    const __half* Ah = (mode == 0) ? g_Xq : (mode == 3) ? g_O : g_Xkv;
    const __half* Wh = g_WTh + ((size_t)mode << 20);
    const float* bias = (mode == 0) ? b0 : (mode == 1) ? b1 : (mode == 2) ? b2 : b3;

    const int tid = threadIdx.x;
    const int lane = tid & 31, wid = tid >> 5;
    const int g = lane >> 2, t = lane & 3;
    const int wm = wid & 1, wn = wid >> 1;
    const int m0 = blockIdx.y * 128, n0 = blockIdx.x * 128;

    const int crow = tid >> 3, cc = tid & 7;   // 16 base rows x 8 col-chunks

    float c[4][8][4];
#pragma unroll
    for (int i = 0; i < 4; i++)
#pragma unroll
        for (int j = 0; j < 8; j++)
#pragma unroll
            for (int k = 0; k < 4; k++) c[i][j][k] = 0.0f;

    auto issue = [&](int stage, int s) {
        const uint32_t aoff = s * TB_SZ, boff = 2 * TB_SZ + s * TB_SZ;
#pragma unroll
        for (int q = 0; q < 8; q++) {
            int row = crow + 16 * q;
            cpa16(sbase + (aoff + row * SP2 + cc * 4) * 4,
                  Ah + (size_t)(m0 + row) * D_ + stage * 64 + cc * 8);
            cpa16(sbase + (boff + row * SP2 + cc * 4) * 4,
                  Wh + (size_t)(n0 + row) * D_ + stage * 64 + cc * 8);
        }
    };

    issue(0, 0); CPA_COMMIT();

    for (int kt = 0; kt < 16; kt++) {
        CPA_WAIT0();
        __syncthreads();
        if (kt < 15) { issue(kt + 1, (kt + 1) & 1); CPA_COMMIT(); }
        const uint32_t* As = smp + (kt & 1) * TB_SZ;
        const uint32_t* Bs = smp + 2 * TB_SZ + (kt & 1) * TB_SZ;
#pragma unroll
        for (int kb = 0; kb < 4; kb++) {
            const int k0 = 8 * kb;
            uint32_t a[4][4];
#pragma unroll
            for (int mt = 0; mt < 4; mt++) {
                int r = wm * 64 + mt * 16 + g;
                a[mt][0] = As[r * SP2 + k0 + t];
                a[mt][1] = As[(r + 8) * SP2 + k0 + t];
                a[mt][2] = As[r * SP2 + k0 + t + 4];
                a[mt][3] = As[(r + 8) * SP2 + k0 + t + 4];
            }
#pragma unroll
            for (int nt = 0; nt < 8; nt++) {
                int n = wn * 64 + nt * 8 + g;
                uint32_t b[2];
                b[0] = Bs[n * SP2 + k0 + t];
                b[1] = Bs[n * SP2 + k0 + t + 4];
                MMA_F16(c[0][nt], a[0], b);
                MMA_F16(c[1][nt], a[1], b);
                MMA_F16(c[2][nt], a[2], b);
                MMA_F16(c[3][nt], a[3], b);
            }
        }
    }

    // epilogue
#pragma unroll
    for (int mt = 0; mt < 4; mt++) {
        int r0 = m0 + wm * 64 + mt * 16 + g;
        int r1 = r0 + 8;
#pragma unroll
        for (int nt = 0; nt < 8; nt++) {
            int col = n0 + wn * 64 + nt * 8 + 2 * t;
            float2 bb = *(const float2*)&bias[col];
            float v00 = c[mt][nt][0] + bb.x, v01 = c[mt][nt][1] + bb.y;
            float v10 = c[mt][nt][2] + bb.x, v11 = c[mt][nt][3] + bb.y;
            if (mode == 0) {
                v00 *= SCALE_Q; v01 *= SCALE_Q; v10 *= SCALE_Q; v11 *= SCALE_Q;
            }
            if (mode == 3) {
                *(float2*)&Cout[(size_t)r0 * D_ + col] = make_float2(v00, v01);
                *(float2*)&Cout[(size_t)r1 * D_ + col] = make_float2(v10, v11);
            } else {
                __half* dst = (mode == 0) ? g_Q : (mode == 1) ? g_K : g_V;
                int hh = col >> 6, hd = col & 63;
                {
                    int bb2 = r0 >> 11, n = r0 & 2047;
                    *(__half2*)(dst + (((size_t)(bb2 * H_ + hh)) * 2048 + n) * HD_ + hd) =
                        __floats2half2_rn(v00, v01);
                }
                {
                    int bb2 = r1 >> 11, n = r1 & 2047;
                    *(__half2*)(dst + (((size_t)(bb2 * H_ + hh)) * 2048 + n) * HD_ + hd) =
                        __floats2half2_rn(v10, v11);
                }
            }
        }
    }
}

// ---------------------------------------------------------------------------
// fp16 flash attention, cp.async double-buffered K/V, 1 sync per iteration.
// (unchanged from round 12 — best measured)
// ---------------------------------------------------------------------------
#define SK2 36
#define QS_SZ (128 * SK2)
#define KV_SZ (64 * SK2)
#define ATTN_SMEM ((QS_SZ + 4 * KV_SZ) * 4 + 2 * 64 * 4)

__global__ void __launch_bounds__(128, 2)
attnh()
{
    extern __shared__ uint32_t smA[];
    uint32_t* Qs = smA;
    uint32_t* Ksb = smA + QS_SZ;
    uint32_t* Vsb = smA + QS_SZ + 2 * KV_SZ;
    float* Mbb = (float*)(smA + QS_SZ + 4 * KV_SZ);
    const uint32_t sbase = smem_u32(smA);

    const int tid = threadIdx.x;
    const int lane = tid & 31, wid = tid >> 5;
    const int g = lane >> 2, t = lane & 3;
    const int bh = blockIdx.y;
    const int b = bh >> 4, h = bh & 15;
    const int qt = blockIdx.x;

    const __half* Qp = g_Q + ((size_t)bh * N_ + qt * 128) * HD_;
    const __half* Kp = g_K + (size_t)bh * L_ * HD_;
    const __half* Vtp = g_VT + (size_t)bh * HD_ * L_;
    const unsigned char* mp = g_mask + b * L_;

#pragma unroll
    for (int q = 0; q < 8; q++) {
        int idx = tid + 128 * q;
        int row = idx >> 3, cu = (idx & 7) * 4;
        *(uint4*)&Qs[row * SK2 + cu] = *(const uint4*)(Qp + (size_t)row * HD_ + (idx & 7) * 8);
    }

    auto issue_kv = [&](int tt, int s) {
#pragma unroll
        for (int q = 0; q < 4; q++) {
            int idx = tid + 128 * q;
            int row = idx >> 3, ch = idx & 7;
            cpa16(sbase + (QS_SZ + s * KV_SZ + row * SK2 + ch * 4) * 4,
                  Kp + (size_t)(tt * 64 + row) * HD_ + ch * 8);
            cpa16(sbase + (QS_SZ + 2 * KV_SZ + s * KV_SZ + row * SK2 + ch * 4) * 4,
                  Vtp + (size_t)row * L_ + tt * 64 + ch * 8);
        }
    };
    auto load_mb = [&](int tt, int s) {
        if (tid < 16) {
            uchar4 mv = *(const uchar4*)(mp + tt * 64 + tid * 4);
            float* Mb = Mbb + s * 64;
            Mb[tid * 4 + 0] = mv.x ? MASKBIAS : 0.0f;
            Mb[tid * 4 + 1] = mv.y ? MASKBIAS : 0.0f;
            Mb[tid * 4 + 2] = mv.z ? MASKBIAS : 0.0f;
            Mb[tid * 4 + 3] = mv.w ? MASKBIAS : 0.0f;
        }
    };

    issue_kv(0, 0); CPA_COMMIT();
    load_mb(0, 0);

    float m[4], l[4];
    float oc[2][8][4];
#pragma unroll
    for (int s = 0; s < 4; s++) { m[s] = MINIT; l[s] = 0.0f; }
#pragma unroll
    for (int mt = 0; mt < 2; mt++)
#pragma unroll
        for (int nt = 0; nt < 8; nt++)
#pragma unroll
            for (int j = 0; j < 4; j++) oc[mt][nt][j] = 0.0f;

    const int R = wid * 32;
    const int NT = L_ / 64;

    for (int tt = 0; tt < NT; tt++) {
        const int cb = tt & 1;
        CPA_WAIT0();
        __syncthreads();
        if (tt + 1 < NT) issue_kv(tt + 1, cb ^ 1);
        CPA_COMMIT();
        if (tt + 1 < NT) load_mb(tt + 1, cb ^ 1);

        const uint32_t* Ks = Ksb + cb * KV_SZ;
        const uint32_t* Vs = Vsb + cb * KV_SZ;
        const float* Mb = Mbb + cb * 64;

        float sc[2][8][4];
#pragma unroll
        for (int mt = 0; mt < 2; mt++)
#pragma unroll
            for (int nt = 0; nt < 8; nt++)
#pragma unroll
                for (int j = 0; j < 4; j++) sc[mt][nt][j] = 0.0f;
#pragma unroll
        for (int kb = 0; kb < 4; kb++) {
            const int k0 = 8 * kb;
            uint32_t aq[2][4];
#pragma unroll
            for (int mt = 0; mt < 2; mt++) {
                int r = R + mt * 16 + g;
                aq[mt][0] = Qs[r * SK2 + k0 + t];
                aq[mt][1] = Qs[(r + 8) * SK2 + k0 + t];
                aq[mt][2] = Qs[r * SK2 + k0 + t + 4];
                aq[mt][3] = Qs[(r + 8) * SK2 + k0 + t + 4];
            }
#pragma unroll
            for (int nt = 0; nt < 8; nt++) {
                int n = nt * 8 + g;
                uint32_t bk[2];
                bk[0] = Ks[n * SK2 + k0 + t];
                bk[1] = Ks[n * SK2 + k0 + t + 4];
                MMA_F16(sc[0][nt], aq[0], bk);
                MMA_F16(sc[1][nt], aq[1], bk);
            }
        }

#pragma unroll
        for (int nt = 0; nt < 8; nt++) {
            float2 mb = *(const float2*)&Mb[nt * 8 + 2 * t];
#pragma unroll
            for (int mt = 0; mt < 2; mt++) {
                sc[mt][nt][0] += mb.x; sc[mt][nt][1] += mb.y;
                sc[mt][nt][2] += mb.x; sc[mt][nt][3] += mb.y;
            }
        }

        float tm[4];
#pragma unroll
        for (int s = 0; s < 4; s++) tm[s] = -3.0e38f;
#pragma unroll
        for (int mt = 0; mt < 2; mt++)
#pragma unroll
            for (int nt = 0; nt < 8; nt++) {
                tm[mt * 2 + 0] = fmaxf(tm[mt * 2 + 0], fmaxf(sc[mt][nt][0], sc[mt][nt][1]));
                tm[mt * 2 + 1] = fmaxf(tm[mt * 2 + 1], fmaxf(sc[mt][nt][2], sc[mt][nt][3]));
            }
#pragma unroll
        for (int off = 1; off < 4; off <<= 1)
#pragma unroll
            for (int s = 0; s < 4; s++)
                tm[s] = fmaxf(tm[s], __shfl_xor_sync(0xffffffffu, tm[s], off));

        float al[4], rs[4];
#pragma unroll
        for (int s = 0; s < 4; s++) {
            float mn = fmaxf(m[s], tm[s]);
            al[s] = ex2f(m[s] - mn);
            m[s] = mn;
            rs[s] = 0.0f;
        }
#pragma unroll
        for (int mt = 0; mt < 2; mt++)
#pragma unroll
            for (int nt = 0; nt < 8; nt++) {
                sc[mt][nt][0] = ex2f(sc[mt][nt][0] - m[mt * 2 + 0]);
                sc[mt][nt][1] = ex2f(sc[mt][nt][1] - m[mt * 2 + 0]);
                sc[mt][nt][2] = ex2f(sc[mt][nt][2] - m[mt * 2 + 1]);
                sc[mt][nt][3] = ex2f(sc[mt][nt][3] - m[mt * 2 + 1]);
                rs[mt * 2 + 0] += sc[mt][nt][0] + sc[mt][nt][1];
                rs[mt * 2 + 1] += sc[mt][nt][2] + sc[mt][nt][3];
            }
#pragma unroll
        for (int off = 1; off < 4; off <<= 1)
#pragma unroll
            for (int s = 0; s < 4; s++)
                rs[s] += __shfl_xor_sync(0xffffffffu, rs[s], off);
#pragma unroll
        for (int s = 0; s < 4; s++) l[s] = l[s] * al[s] + rs[s];
#pragma unroll
        for (int mt = 0; mt < 2; mt++)
#pragma unroll
            for (int nt = 0; nt < 8; nt++) {
                oc[mt][nt][0] *= al[mt * 2 + 0]; oc[mt][nt][1] *= al[mt * 2 + 0];
                oc[mt][nt][2] *= al[mt * 2 + 1]; oc[mt][nt][3] *= al[mt * 2 + 1];
            }

#pragma unroll
        for (int j = 0; j < 4; j++) {
            const int k0 = 8 * j;
            uint32_t ap[2][4];
#pragma unroll
            for (int mt = 0; mt < 2; mt++) {
                ap[mt][0] = h2pack(sc[mt][2 * j][0], sc[mt][2 * j][1]);
                ap[mt][1] = h2pack(sc[mt][2 * j][2], sc[mt][2 * j][3]);
                ap[mt][2] = h2pack(sc[mt][2 * j + 1][0], sc[mt][2 * j + 1][1]);
                ap[mt][3] = h2pack(sc[mt][2 * j + 1][2], sc[mt][2 * j + 1][3]);
            }
#pragma unroll
            for (int nt = 0; nt < 8; nt++) {
                int n = nt * 8 + g;
                uint32_t bv[2];
                bv[0] = Vs[n * SK2 + k0 + t];
                bv[1] = Vs[n * SK2 + k0 + t + 4];
                MMA_F16(oc[0][nt], ap[0], bv);
                MMA_F16(oc[1][nt], ap[1], bv);
            }
        }
    }

    float inv[4];
#pragma unroll
    for (int s = 0; s < 4; s++) inv[s] = 1.0f / l[s];
#pragma unroll
    for (int mt = 0; mt < 2; mt++) {
        int n0r = qt * 128 + R + mt * 16 + g;
        int n1r = n0r + 8;
#pragma unroll
        for (int nt = 0; nt < 8; nt++) {
            int cc = nt * 8 + 2 * t;
            *(__half2*)(g_O + ((size_t)(b * N_ + n0r)) * D_ + h * HD_ + cc) =
                __floats2half2_rn(oc[mt][nt][0] * inv[mt * 2 + 0],
                                  oc[mt][nt][1] * inv[mt * 2 + 0]);
            *(__half2*)(g_O + ((size_t)(b * N_ + n1r)) * D_ + h * HD_ + cc) =
                __floats2half2_rn(oc[mt][nt][2] * inv[mt * 2 + 1],
                                  oc[mt][nt][3] * inv[mt * 2 + 1]);
        }
    }
}

// ---------------------------------------------------------------------------
extern "C" void kernel_launch(void* const* d_in, const int* in_sizes, int n_in,
                              void* d_out, int out_size)
{
    (void)in_sizes; (void)n_in; (void)out_size;
    const float* x_q  = (const float*)d_in[0];
    const float* x_kv = (const float*)d_in[1];
    const void*  mraw = d_in[2];
    const float* wq = (const float*)d_in[3];
    const float* bq = (const float*)d_in[4];
    const float* wk = (const float*)d_in[5];
    const float* bk = (const float*)d_in[6];
    const float* wv = (const float*)d_in[7];
    const float* bv = (const float*)d_in[8];
    const float* wo = (const float*)d_in[9];
    const float* bo = (const float*)d_in[10];
    float* out = (float*)d_out;

    static int attr_done = 0;
    if (!attr_done) {
        cudaFuncSetAttribute(projp, cudaFuncAttributeMaxDynamicSharedMemorySize, PR_SMEM);
        cudaFuncSetAttribute(attnh, cudaFuncAttributeMaxDynamicSharedMemorySize, ATTN_SMEM);
        attr_done = 1;
    }

    mask_prep<<<1, 1024>>>(mraw);
    cvt_x<<<4096, 256>>>(x_q, x_kv);
    wt_cvt<<<dim3(32, 32, 4), dim3(32, 8)>>>(wq, wk, wv, wo);

    projp<<<dim3(8, 32, 3), 128, PR_SMEM>>>(0, bq, bk, bv, bo, nullptr);

    vtrans<<<dim3(64, 2, 32), dim3(32, 8)>>>();

    attnh<<<dim3(N_ / 128, B_ * H_), 128, ATTN_SMEM>>>();

    projp<<<dim3(8, 32, 1), 128, PR_SMEM>>>(3, bq, bk, bv, bo, out);
}

// round 15
// speedup vs baseline: 3.1057x; 1.0255x over previous
#include <cuda_runtime.h>
#include <cuda_fp16.h>
#include <cstdint>

#define B_ 2
#define N_ 2048
#define L_ 2048
#define D_ 1024
#define H_ 16
#define HD_ 64
#define LOG2E 1.4426950408889634f
#define SCALE_Q (0.125f * LOG2E)
#define MASKBIAS (-2.0e30f)
#define MINIT (-1.0e30f)

__device__ __half g_Xq[(size_t)B_ * N_ * D_];
__device__ __half g_Xkv[(size_t)B_ * L_ * D_];
__device__ __half g_WTh[4 * 1024 * 1024];            // [z][n][k]
__device__ __half g_Q[(size_t)B_ * H_ * N_ * HD_];   // *SCALE_Q
__device__ __half g_K[(size_t)B_ * H_ * L_ * HD_];
__device__ __half g_VT[(size_t)B_ * H_ * HD_ * L_];  // [bh][d][l]
__device__ __half g_O[(size_t)B_ * N_ * D_];
__device__ unsigned char g_mask[B_ * L_];

__device__ __forceinline__ float ex2f(float x) {
    float r; asm("ex2.approx.ftz.f32 %0, %1;" : "=f"(r) : "f"(x)); return r;
}
__device__ __forceinline__ uint32_t h2pack(float lo, float hi) {
    __half2 h = __floats2half2_rn(lo, hi);
    return *(uint32_t*)&h;
}
__device__ __forceinline__ uint32_t smem_u32(const void* p) {
    uint32_t a;
    asm("{ .reg .u64 t; cvta.to.shared.u64 t, %1; cvt.u32.u64 %0, t; }" : "=r"(a) : "l"(p));
    return a;
}
__device__ __forceinline__ void cpa16(uint32_t dst, const void* src) {
    asm volatile("cp.async.cg.shared.global [%0], [%1], 16;" :: "r"(dst), "l"(src));
}
#define CPA_COMMIT() asm volatile("cp.async.commit_group;" ::: "memory")
#define CPA_WAIT0()  asm volatile("cp.async.wait_group 0;" ::: "memory")

#define MMA_F16(C, A, Bf) \
    asm volatile("mma.sync.aligned.m16n8k16.row.col.f32.f16.f16.f32 " \
        "{%0,%1,%2,%3},{%4,%5,%6,%7},{%8,%9},{%0,%1,%2,%3};" \
        : "+f"((C)[0]), "+f"((C)[1]), "+f"((C)[2]), "+f"((C)[3]) \
        : "r"((A)[0]), "r"((A)[1]), "r"((A)[2]), "r"((A)[3]), "r"((Bf)[0]), "r"((Bf)[1]))

// ---------------------------------------------------------------------------
// Fused prep: blockIdx.x in [0,4096) -> cvt_x chunk; [4096,8192) -> wt_cvt
// tile; 8192 -> mask canonicalization. 256 threads everywhere.
// ---------------------------------------------------------------------------
__global__ void prep(const float* __restrict__ xq, const float* __restrict__ xkv,
                     const float* __restrict__ w0, const float* __restrict__ w1,
                     const float* __restrict__ w2, const float* __restrict__ w3,
                     const void* __restrict__ mraw)
{
    const int bx = blockIdx.x;
    const int tid = threadIdx.x;

    if (bx < 4096) {
        int i = bx * 256 + tid;
        float4 a = ((const float4*)xq)[i];
        float4 b = ((const float4*)xkv)[i];
        __half2* q2 = (__half2*)g_Xq;
        __half2* k2 = (__half2*)g_Xkv;
        q2[2 * i]     = __floats2half2_rn(a.x, a.y);
        q2[2 * i + 1] = __floats2half2_rn(a.z, a.w);
        k2[2 * i]     = __floats2half2_rn(b.x, b.y);
        k2[2 * i + 1] = __floats2half2_rn(b.z, b.w);
    } else if (bx < 8192) {
        __shared__ float t[32][33];
        int idx = bx - 4096;
        int z = idx >> 10, r = idx & 1023;
        const float* src = (z == 0) ? w0 : (z == 1) ? w1 : (z == 2) ? w2 : w3;
        __half* dst = g_WTh + ((size_t)z << 20);
        int bxt = (r & 31) * 32, byt = (r >> 5) * 32;
        int x = tid & 31, y0 = tid >> 5;   // (32, 8)
#pragma unroll
        for (int i = 0; i < 32; i += 8)
            t[y0 + i][x] = src[(size_t)(byt + y0 + i) * 1024 + bxt + x];
        __syncthreads();
#pragma unroll
        for (int i = 0; i < 32; i += 8)
            dst[(size_t)(bxt + y0 + i) * 1024 + byt + x] = __float2half(t[x][y0 + i]);
    } else {
        __shared__ int s_isf, s_nb;
        if (tid == 0) { s_isf = 0; s_nb = 0; }
        __syncthreads();
        const int* ip = (const int*)mraw;
#pragma unroll
        for (int q = 0; q < 4; q++) {
            int v = ip[tid * 4 + q];
            if (v == 0x3F800000) atomicExch(&s_isf, 1);
            if (v != 0 && v != 1) atomicExch(&s_nb, 1);
        }
        __syncthreads();
        int mode = s_isf ? 2 : (s_nb ? 1 : 0);
        const unsigned char* bp = (const unsigned char*)mraw;
        const float* fp = (const float*)mraw;
        for (int i = tid; i < B_ * L_; i += 256) {
            unsigned char mv;
            if (mode == 0)      mv = ip[i] != 0;
            else if (mode == 1) mv = bp[i] != 0;
            else                mv = fp[i] != 0.0f;
            g_mask[i] = mv;
        }
    }
}

// ---------------------------------------------------------------------------
// fp16 GEMM, cp.async double-buffered, BK=64, CTA 128x128, 4 warps (2x2,
// warp tile 64x64), 2 CTAs/SM. Runtime mode: 0:Q(*SCALE_Q) 1:K
// 2:V (writes V^T via smem-transpose epilogue) 3:out-proj (fp32 out).
// smem u32: [A0][A1][B0][B1], each 128*36 -> 73728 B/CTA.
// ---------------------------------------------------------------------------
#define SP2 36
#define TB_SZ (128 * SP2)
#define PR_SMEM (4 * TB_SZ * 4)

__global__ void __launch_bounds__(128, 2)
projp(int mode_base, const float* __restrict__ b0, const float* __restrict__ b1,
      const float* __restrict__ b2, const float* __restrict__ b3,
      float* __restrict__ Cout)
{
    extern __shared__ uint32_t smp[];
    const uint32_t sbase = smem_u32(smp);
    const int mode = mode_base + blockIdx.z;

    const __half* Ah = (mode == 0) ? g_Xq : (mode == 3) ? g_O : g_Xkv;
    const __half* Wh = g_WTh + ((size_t)mode << 20);
    const float* bias = (mode == 0) ? b0 : (mode == 1) ? b1 : (mode == 2) ? b2 : b3;

    const int tid = threadIdx.x;
    const int lane = tid & 31, wid = tid >> 5;
    const int g = lane >> 2, t = lane & 3;
    const int wm = wid & 1, wn = wid >> 1;
    const int m0 = blockIdx.y * 128, n0 = blockIdx.x * 128;

    const int crow = tid >> 3, cc = tid & 7;

    float c[4][8][4];
#pragma unroll
    for (int i = 0; i < 4; i++)
#pragma unroll
        for (int j = 0; j < 8; j++)
#pragma unroll
            for (int k = 0; k < 4; k++) c[i][j][k] = 0.0f;

    auto issue = [&](int stage, int s) {
        const uint32_t aoff = s * TB_SZ, boff = 2 * TB_SZ + s * TB_SZ;
#pragma unroll
        for (int q = 0; q < 8; q++) {
            int row = crow + 16 * q;
            cpa16(sbase + (aoff + row * SP2 + cc * 4) * 4,
                  Ah + (size_t)(m0 + row) * D_ + stage * 64 + cc * 8);
            cpa16(sbase + (boff + row * SP2 + cc * 4) * 4,
                  Wh + (size_t)(n0 + row) * D_ + stage * 64 + cc * 8);
        }
    };

    issue(0, 0); CPA_COMMIT();

    for (int kt = 0; kt < 16; kt++) {
        CPA_WAIT0();
        __syncthreads();
        if (kt < 15) { issue(kt + 1, (kt + 1) & 1); CPA_COMMIT(); }
        const uint32_t* As = smp + (kt & 1) * TB_SZ;
        const uint32_t* Bs = smp + 2 * TB_SZ + (kt & 1) * TB_SZ;
#pragma unroll
        for (int kb = 0; kb < 4; kb++) {
            const int k0 = 8 * kb;
            uint32_t a[4][4];
#pragma unroll
            for (int mt = 0; mt < 4; mt++) {
                int r = wm * 64 + mt * 16 + g;
                a[mt][0] = As[r * SP2 + k0 + t];
                a[mt][1] = As[(r + 8) * SP2 + k0 + t];
                a[mt][2] = As[r * SP2 + k0 + t + 4];
                a[mt][3] = As[(r + 8) * SP2 + k0 + t + 4];
            }
#pragma unroll
            for (int nt = 0; nt < 8; nt++) {
                int n = wn * 64 + nt * 8 + g;
                uint32_t b[2];
                b[0] = Bs[n * SP2 + k0 + t];
                b[1] = Bs[n * SP2 + k0 + t + 4];
                MMA_F16(c[0][nt], a[0], b);
                MMA_F16(c[1][nt], a[1], b);
                MMA_F16(c[2][nt], a[2], b);
                MMA_F16(c[3][nt], a[3], b);
            }
        }
    }

    if (mode == 2) {
        // V-projection: transpose in smem, write V^T [bh][d][l] coalesced.
        __syncthreads();                 // all warps done reading smem buffers
        __half* stg = (__half*)smp;      // 128 cols x 136 halves (34816 B)
#pragma unroll
        for (int mt = 0; mt < 4; mt++) {
            int r0l = wm * 64 + mt * 16 + g;
            int r1l = r0l + 8;
#pragma unroll
            for (int nt = 0; nt < 8; nt++) {
                int cl = wn * 64 + nt * 8 + 2 * t;
                float2 bb = *(const float2*)&bias[n0 + cl];
                stg[cl * 136 + r0l]       = __float2half(c[mt][nt][0] + bb.x);
                stg[(cl + 1) * 136 + r0l] = __float2half(c[mt][nt][1] + bb.y);
                stg[cl * 136 + r1l]       = __float2half(c[mt][nt][2] + bb.x);
                stg[(cl + 1) * 136 + r1l] = __float2half(c[mt][nt][3] + bb.y);
            }
        }
        __syncthreads();
        int cgl = n0 + tid;              // global feature col
        int hh = cgl >> 6, hd = cgl & 63;
        int bb2 = m0 >> 11, l0 = m0 & 2047;
        __half* dst = g_VT + ((size_t)(bb2 * H_ + hh) * HD_ + hd) * L_ + l0;
#pragma unroll
        for (int q = 0; q < 16; q++)     // 16 chunks x 8 halves = 128 halves
            *(uint4*)(dst + q * 8) = *(const uint4*)&stg[tid * 136 + q * 8];
        return;
    }

    // epilogue (Q, K, out-proj)
#pragma unroll
    for (int mt = 0; mt < 4; mt++) {
        int r0 = m0 + wm * 64 + mt * 16 + g;
        int r1 = r0 + 8;
#pragma unroll
        for (int nt = 0; nt < 8; nt++) {
            int col = n0 + wn * 64 + nt * 8 + 2 * t;
            float2 bb = *(const float2*)&bias[col];
            float v00 = c[mt][nt][0] + bb.x, v01 = c[mt][nt][1] + bb.y;
            float v10 = c[mt][nt][2] + bb.x, v11 = c[mt][nt][3] + bb.y;
            if (mode == 0) {
                v00 *= SCALE_Q; v01 *= SCALE_Q; v10 *= SCALE_Q; v11 *= SCALE_Q;
            }
            if (mode == 3) {
                *(float2*)&Cout[(size_t)r0 * D_ + col] = make_float2(v00, v01);
                *(float2*)&Cout[(size_t)r1 * D_ + col] = make_float2(v10, v11);
            } else {
                __half* dst = (mode == 0) ? g_Q : g_K;
                int hh = col >> 6, hd = col & 63;
                {
                    int bb2 = r0 >> 11, n = r0 & 2047;
                    *(__half2*)(dst + (((size_t)(bb2 * H_ + hh)) * 2048 + n) * HD_ + hd) =
                        __floats2half2_rn(v00, v01);
                }
                {
                    int bb2 = r1 >> 11, n = r1 & 2047;
                    *(__half2*)(dst + (((size_t)(bb2 * H_ + hh)) * 2048 + n) * HD_ + hd) =
                        __floats2half2_rn(v10, v11);
                }
            }
        }
    }
}

// ---------------------------------------------------------------------------
// fp16 flash attention, cp.async double-buffered K/V, 1 sync per iteration.
// (unchanged — at the fp16 mma.sync ceiling)
// ---------------------------------------------------------------------------
#define SK2 36
#define QS_SZ (128 * SK2)
#define KV_SZ (64 * SK2)
#define ATTN_SMEM ((QS_SZ + 4 * KV_SZ) * 4 + 2 * 64 * 4)

__global__ void __launch_bounds__(128, 2)
attnh()
{
    extern __shared__ uint32_t smA[];
    uint32_t* Qs = smA;
    uint32_t* Ksb = smA + QS_SZ;
    uint32_t* Vsb = smA + QS_SZ + 2 * KV_SZ;
    float* Mbb = (float*)(smA + QS_SZ + 4 * KV_SZ);
    const uint32_t sbase = smem_u32(smA);

    const int tid = threadIdx.x;
    const int lane = tid & 31, wid = tid >> 5;
    const int g = lane >> 2, t = lane & 3;
    const int bh = blockIdx.y;
    const int b = bh >> 4, h = bh & 15;
    const int qt = blockIdx.x;

    const __half* Qp = g_Q + ((size_t)bh * N_ + qt * 128) * HD_;
    const __half* Kp = g_K + (size_t)bh * L_ * HD_;
    const __half* Vtp = g_VT + (size_t)bh * HD_ * L_;
    const unsigned char* mp = g_mask + b * L_;

#pragma unroll
    for (int q = 0; q < 8; q++) {
        int idx = tid + 128 * q;
        int row = idx >> 3, cu = (idx & 7) * 4;
        *(uint4*)&Qs[row * SK2 + cu] = *(const uint4*)(Qp + (size_t)row * HD_ + (idx & 7) * 8);
    }

    auto issue_kv = [&](int tt, int s) {
#pragma unroll
        for (int q = 0; q < 4; q++) {
            int idx = tid + 128 * q;
            int row = idx >> 3, ch = idx & 7;
            cpa16(sbase + (QS_SZ + s * KV_SZ + row * SK2 + ch * 4) * 4,
                  Kp + (size_t)(tt * 64 + row) * HD_ + ch * 8);
            cpa16(sbase + (QS_SZ + 2 * KV_SZ + s * KV_SZ + row * SK2 + ch * 4) * 4,
                  Vtp + (size_t)row * L_ + tt * 64 + ch * 8);
        }
    };
    auto load_mb = [&](int tt, int s) {
        if (tid < 16) {
            uchar4 mv = *(const uchar4*)(mp + tt * 64 + tid * 4);
            float* Mb = Mbb + s * 64;
            Mb[tid * 4 + 0] = mv.x ? MASKBIAS : 0.0f;
            Mb[tid * 4 + 1] = mv.y ? MASKBIAS : 0.0f;
            Mb[tid * 4 + 2] = mv.z ? MASKBIAS : 0.0f;
            Mb[tid * 4 + 3] = mv.w ? MASKBIAS : 0.0f;
        }
    };

    issue_kv(0, 0); CPA_COMMIT();
    load_mb(0, 0);

    float m[4], l[4];
    float oc[2][8][4];
#pragma unroll
    for (int s = 0; s < 4; s++) { m[s] = MINIT; l[s] = 0.0f; }
#pragma unroll
    for (int mt = 0; mt < 2; mt++)
#pragma unroll
        for (int nt = 0; nt < 8; nt++)
#pragma unroll
            for (int j = 0; j < 4; j++) oc[mt][nt][j] = 0.0f;

    const int R = wid * 32;
    const int NT = L_ / 64;

    for (int tt = 0; tt < NT; tt++) {
        const int cb = tt & 1;
        CPA_WAIT0();
        __syncthreads();
        if (tt + 1 < NT) issue_kv(tt + 1, cb ^ 1);
        CPA_COMMIT();
        if (tt + 1 < NT) load_mb(tt + 1, cb ^ 1);

        const uint32_t* Ks = Ksb + cb * KV_SZ;
        const uint32_t* Vs = Vsb + cb * KV_SZ;
        const float* Mb = Mbb + cb * 64;

        float sc[2][8][4];
#pragma unroll
        for (int mt = 0; mt < 2; mt++)
#pragma unroll
            for (int nt = 0; nt < 8; nt++)
#pragma unroll
                for (int j = 0; j < 4; j++) sc[mt][nt][j] = 0.0f;
#pragma unroll
        for (int kb = 0; kb < 4; kb++) {
            const int k0 = 8 * kb;
            uint32_t aq[2][4];
#pragma unroll
            for (int mt = 0; mt < 2; mt++) {
                int r = R + mt * 16 + g;
                aq[mt][0] = Qs[r * SK2 + k0 + t];
                aq[mt][1] = Qs[(r + 8) * SK2 + k0 + t];
                aq[mt][2] = Qs[r * SK2 + k0 + t + 4];
                aq[mt][3] = Qs[(r + 8) * SK2 + k0 + t + 4];
            }
#pragma unroll
            for (int nt = 0; nt < 8; nt++) {
                int n = nt * 8 + g;
                uint32_t bk[2];
                bk[0] = Ks[n * SK2 + k0 + t];
                bk[1] = Ks[n * SK2 + k0 + t + 4];
                MMA_F16(sc[0][nt], aq[0], bk);
                MMA_F16(sc[1][nt], aq[1], bk);
            }
        }

#pragma unroll
        for (int nt = 0; nt < 8; nt++) {
            float2 mb = *(const float2*)&Mb[nt * 8 + 2 * t];
#pragma unroll
            for (int mt = 0; mt < 2; mt++) {
                sc[mt][nt][0] += mb.x; sc[mt][nt][1] += mb.y;
                sc[mt][nt][2] += mb.x; sc[mt][nt][3] += mb.y;
            }
        }

        float tm[4];
#pragma unroll
        for (int s = 0; s < 4; s++) tm[s] = -3.0e38f;
#pragma unroll
        for (int mt = 0; mt < 2; mt++)
#pragma unroll
            for (int nt = 0; nt < 8; nt++) {
                tm[mt * 2 + 0] = fmaxf(tm[mt * 2 + 0], fmaxf(sc[mt][nt][0], sc[mt][nt][1]));
                tm[mt * 2 + 1] = fmaxf(tm[mt * 2 + 1], fmaxf(sc[mt][nt][2], sc[mt][nt][3]));
            }
#pragma unroll
        for (int off = 1; off < 4; off <<= 1)
#pragma unroll
            for (int s = 0; s < 4; s++)
                tm[s] = fmaxf(tm[s], __shfl_xor_sync(0xffffffffu, tm[s], off));

        float al[4], rs[4];
#pragma unroll
        for (int s = 0; s < 4; s++) {
            float mn = fmaxf(m[s], tm[s]);
            al[s] = ex2f(m[s] - mn);
            m[s] = mn;
            rs[s] = 0.0f;
        }
#pragma unroll
        for (int mt = 0; mt < 2; mt++)
#pragma unroll
            for (int nt = 0; nt < 8; nt++) {
                sc[mt][nt][0] = ex2f(sc[mt][nt][0] - m[mt * 2 + 0]);
                sc[mt][nt][1] = ex2f(sc[mt][nt][1] - m[mt * 2 + 0]);
                sc[mt][nt][2] = ex2f(sc[mt][nt][2] - m[mt * 2 + 1]);
                sc[mt][nt][3] = ex2f(sc[mt][nt][3] - m[mt * 2 + 1]);
                rs[mt * 2 + 0] += sc[mt][nt][0] + sc[mt][nt][1];
                rs[mt * 2 + 1] += sc[mt][nt][2] + sc[mt][nt][3];
            }
#pragma unroll
        for (int off = 1; off < 4; off <<= 1)
#pragma unroll
            for (int s = 0; s < 4; s++)
                rs[s] += __shfl_xor_sync(0xffffffffu, rs[s], off);
#pragma unroll
        for (int s = 0; s < 4; s++) l[s] = l[s] * al[s] + rs[s];
#pragma unroll
        for (int mt = 0; mt < 2; mt++)
#pragma unroll
            for (int nt = 0; nt < 8; nt++) {
                oc[mt][nt][0] *= al[mt * 2 + 0]; oc[mt][nt][1] *= al[mt * 2 + 0];
                oc[mt][nt][2] *= al[mt * 2 + 1]; oc[mt][nt][3] *= al[mt * 2 + 1];
            }

#pragma unroll
        for (int j = 0; j < 4; j++) {
            const int k0 = 8 * j;
            uint32_t ap[2][4];
#pragma unroll
            for (int mt = 0; mt < 2; mt++) {
                ap[mt][0] = h2pack(sc[mt][2 * j][0], sc[mt][2 * j][1]);
                ap[mt][1] = h2pack(sc[mt][2 * j][2], sc[mt][2 * j][3]);
                ap[mt][2] = h2pack(sc[mt][2 * j + 1][0], sc[mt][2 * j + 1][1]);
                ap[mt][3] = h2pack(sc[mt][2 * j + 1][2], sc[mt][2 * j + 1][3]);
            }
#pragma unroll
            for (int nt = 0; nt < 8; nt++) {
                int n = nt * 8 + g;
                uint32_t bv[2];
                bv[0] = Vs[n * SK2 + k0 + t];
                bv[1] = Vs[n * SK2 + k0 + t + 4];
                MMA_F16(oc[0][nt], ap[0], bv);
                MMA_F16(oc[1][nt], ap[1], bv);
            }
        }
    }

    float inv[4];
#pragma unroll
    for (int s = 0; s < 4; s++) inv[s] = 1.0f / l[s];
#pragma unroll
    for (int mt = 0; mt < 2; mt++) {
        int n0r = qt * 128 + R + mt * 16 + g;
        int n1r = n0r + 8;
#pragma unroll
        for (int nt = 0; nt < 8; nt++) {
            int cc = nt * 8 + 2 * t;
            *(__half2*)(g_O + ((size_t)(b * N_ + n0r)) * D_ + h * HD_ + cc) =
                __floats2half2_rn(oc[mt][nt][0] * inv[mt * 2 + 0],
                                  oc[mt][nt][1] * inv[mt * 2 + 0]);
            *(__half2*)(g_O + ((size_t)(b * N_ + n1r)) * D_ + h * HD_ + cc) =
                __floats2half2_rn(oc[mt][nt][2] * inv[mt * 2 + 1],
                                  oc[mt][nt][3] * inv[mt * 2 + 1]);
        }
    }
}

// ---------------------------------------------------------------------------
extern "C" void kernel_launch(void* const* d_in, const int* in_sizes, int n_in,
                              void* d_out, int out_size)
{
    (void)in_sizes; (void)n_in; (void)out_size;
    const float* x_q  = (const float*)d_in[0];
    const float* x_kv = (const float*)d_in[1];
    const void*  mraw = d_in[2];
    const float* wq = (const float*)d_in[3];
    const float* bq = (const float*)d_in[4];
    const float* wk = (const float*)d_in[5];
    const float* bk = (const float*)d_in[6];
    const float* wv = (const float*)d_in[7];
    const float* bv = (const float*)d_in[8];
    const float* wo = (const float*)d_in[9];
    const float* bo = (const float*)d_in[10];
    float* out = (float*)d_out;

    static int attr_done = 0;
    if (!attr_done) {
        cudaFuncSetAttribute(projp, cudaFuncAttributeMaxDynamicSharedMemorySize, PR_SMEM);
        cudaFuncSetAttribute(attnh, cudaFuncAttributeMaxDynamicSharedMemorySize, ATTN_SMEM);
        attr_done = 1;
    }

    prep<<<8193, 256>>>(x_q, x_kv, wq, wk, wv, wo, mraw);

    projp<<<dim3(8, 32, 3), 128, PR_SMEM>>>(0, bq, bk, bv, bo, nullptr);

    attnh<<<dim3(N_ / 128, B_ * H_), 128, ATTN_SMEM>>>();

    projp<<<dim3(8, 32, 1), 128, PR_SMEM>>>(3, bq, bk, bv, bo, out);
}

// round 16
// speedup vs baseline: 3.1988x; 1.0300x over previous
#include <cuda_runtime.h>
#include <cuda_fp16.h>
#include <cstdint>

#define B_ 2
#define N_ 2048
#define L_ 2048
#define D_ 1024
#define H_ 16
#define HD_ 64
#define LOG2E 1.4426950408889634f
#define SCALE_Q (0.125f * LOG2E)
#define MASKBIAS (-2.0e30f)
#define MINIT (-1.0e30f)

__device__ __half g_Xq[(size_t)B_ * N_ * D_];
__device__ __half g_Xkv[(size_t)B_ * L_ * D_];
__device__ __half g_WTh[4 * 1024 * 1024];            // [z][n][k]
__device__ __half g_Q[(size_t)B_ * H_ * N_ * HD_];   // *SCALE_Q
__device__ __half g_K[(size_t)B_ * H_ * L_ * HD_];
__device__ __half g_VT[(size_t)B_ * H_ * HD_ * L_];  // [bh][d][l]
__device__ __half g_O[(size_t)B_ * N_ * D_];
__device__ unsigned char g_mask[B_ * L_];

// dataflow readiness counters (zeroed by prep each call)
__device__ int g_cQ[32 * 8];   // per (m_idx, n_idx) Q tile flag
__device__ int g_cK[2 * 8];    // per (b, n_idx) K count -> 16
__device__ int g_cV[2 * 8];    // per (b, n_idx) V count -> 16
__device__ int g_cA[32];       // per row-block attention count -> 16

__device__ __forceinline__ float ex2f(float x) {
    float r; asm("ex2.approx.ftz.f32 %0, %1;" : "=f"(r) : "f"(x)); return r;
}
__device__ __forceinline__ uint32_t h2pack(float lo, float hi) {
    __half2 h = __floats2half2_rn(lo, hi);
    return *(uint32_t*)&h;
}
__device__ __forceinline__ uint32_t smem_u32(const void* p) {
    uint32_t a;
    asm("{ .reg .u64 t; cvta.to.shared.u64 t, %1; cvt.u32.u64 %0, t; }" : "=r"(a) : "l"(p));
    return a;
}
__device__ __forceinline__ void cpa16(uint32_t dst, const void* src) {
    asm volatile("cp.async.cg.shared.global [%0], [%1], 16;" :: "r"(dst), "l"(src));
}
#define CPA_COMMIT() asm volatile("cp.async.commit_group;" ::: "memory")
#define CPA_WAIT0()  asm volatile("cp.async.wait_group 0;" ::: "memory")

#define MMA_F16(C, A, Bf) \
    asm volatile("mma.sync.aligned.m16n8k16.row.col.f32.f16.f16.f32 " \
        "{%0,%1,%2,%3},{%4,%5,%6,%7},{%8,%9},{%0,%1,%2,%3};" \
        : "+f"((C)[0]), "+f"((C)[1]), "+f"((C)[2]), "+f"((C)[3]) \
        : "r"((A)[0]), "r"((A)[1]), "r"((A)[2]), "r"((A)[3]), "r"((Bf)[0]), "r"((Bf)[1]))

__device__ __forceinline__ void spin_ge(int* p, int target) {
    while (atomicAdd(p, 0) < target) __nanosleep(64);
}

// ---------------------------------------------------------------------------
// Fused prep: [0,4096) cvt_x; [4096,8192) wt_cvt; 8192 mask + counter reset.
// ---------------------------------------------------------------------------
__global__ void prep(const float* __restrict__ xq, const float* __restrict__ xkv,
                     const float* __restrict__ w0, const float* __restrict__ w1,
                     const float* __restrict__ w2, const float* __restrict__ w3,
                     const void* __restrict__ mraw)
{
    const int bx = blockIdx.x;
    const int tid = threadIdx.x;

    if (bx < 4096) {
        int i = bx * 256 + tid;
        float4 a = ((const float4*)xq)[i];
        float4 b = ((const float4*)xkv)[i];
        __half2* q2 = (__half2*)g_Xq;
        __half2* k2 = (__half2*)g_Xkv;
        q2[2 * i]     = __floats2half2_rn(a.x, a.y);
        q2[2 * i + 1] = __floats2half2_rn(a.z, a.w);
        k2[2 * i]     = __floats2half2_rn(b.x, b.y);
        k2[2 * i + 1] = __floats2half2_rn(b.z, b.w);
    } else if (bx < 8192) {
        __shared__ float t[32][33];
        int idx = bx - 4096;
        int z = idx >> 10, r = idx & 1023;
        const float* src = (z == 0) ? w0 : (z == 1) ? w1 : (z == 2) ? w2 : w3;
        __half* dst = g_WTh + ((size_t)z << 20);
        int bxt = (r & 31) * 32, byt = (r >> 5) * 32;
        int x = tid & 31, y0 = tid >> 5;
#pragma unroll
        for (int i = 0; i < 32; i += 8)
            t[y0 + i][x] = src[(size_t)(byt + y0 + i) * 1024 + bxt + x];
        __syncthreads();
#pragma unroll
        for (int i = 0; i < 32; i += 8)
            dst[(size_t)(bxt + y0 + i) * 1024 + byt + x] = __float2half(t[x][y0 + i]);
    } else {
        // counter reset
        if (tid < 256) g_cQ[tid] = 0;
        if (tid < 16) { g_cK[tid] = 0; g_cV[tid] = 0; }
        if (tid < 32) g_cA[tid] = 0;

        __shared__ int s_isf, s_nb;
        if (tid == 0) { s_isf = 0; s_nb = 0; }
        __syncthreads();
        const int* ip = (const int*)mraw;
#pragma unroll
        for (int q = 0; q < 4; q++) {
            int v = ip[tid * 4 + q];
            if (v == 0x3F800000) atomicExch(&s_isf, 1);
            if (v != 0 && v != 1) atomicExch(&s_nb, 1);
        }
        __syncthreads();
        int mode = s_isf ? 2 : (s_nb ? 1 : 0);
        const unsigned char* bp = (const unsigned char*)mraw;
        const float* fp = (const float*)mraw;
        for (int i = tid; i < B_ * L_; i += 256) {
            unsigned char mv;
            if (mode == 0)      mv = ip[i] != 0;
            else if (mode == 1) mv = bp[i] != 0;
            else                mv = fp[i] != 0.0f;
            g_mask[i] = mv;
        }
    }
}

// ---------------------------------------------------------------------------
// GEMM tile body (CTA 128x128, 4 warps, cp.async double-buffered, BK=64).
// ---------------------------------------------------------------------------
#define SP2 36
#define TB_SZ (128 * SP2)
#define PR_SMEM (4 * TB_SZ * 4)

__device__ __forceinline__ void proj_body(
    int mode, int m_idx, int n_idx, uint32_t* smp,
    const float* b0, const float* b1, const float* b2, const float* b3,
    float* Cout)
{
    const uint32_t sbase = smem_u32(smp);
    const __half* Ah = (mode == 0) ? g_Xq : (mode == 3) ? g_O : g_Xkv;
    const __half* Wh = g_WTh + ((size_t)mode << 20);
    const float* bias = (mode == 0) ? b0 : (mode == 1) ? b1 : (mode == 2) ? b2 : b3;

    const int tid = threadIdx.x;
    const int lane = tid & 31, wid = tid >> 5;
    const int g = lane >> 2, t = lane & 3;
    const int wm = wid & 1, wn = wid >> 1;
    const int m0 = m_idx * 128, n0 = n_idx * 128;
    const int crow = tid >> 3, cc = tid & 7;

    float c[4][8][4];
#pragma unroll
    for (int i = 0; i < 4; i++)
#pragma unroll
        for (int j = 0; j < 8; j++)
#pragma unroll
            for (int k = 0; k < 4; k++) c[i][j][k] = 0.0f;

#pragma unroll 1
    for (int kt = 0; kt < 16; kt++) {
        if (kt == 0) {
            const uint32_t aoff = 0, boff = 2 * TB_SZ;
#pragma unroll
            for (int q = 0; q < 8; q++) {
                int row = crow + 16 * q;
                cpa16(sbase + (aoff + row * SP2 + cc * 4) * 4,
                      Ah + (size_t)(m0 + row) * D_ + cc * 8);
                cpa16(sbase + (boff + row * SP2 + cc * 4) * 4,
                      Wh + (size_t)(n0 + row) * D_ + cc * 8);
            }
            CPA_COMMIT();
        }
        CPA_WAIT0();
        __syncthreads();
        if (kt < 15) {
            const int s = (kt + 1) & 1;
            const uint32_t aoff = s * TB_SZ, boff = 2 * TB_SZ + s * TB_SZ;
#pragma unroll
            for (int q = 0; q < 8; q++) {
                int row = crow + 16 * q;
                cpa16(sbase + (aoff + row * SP2 + cc * 4) * 4,
                      Ah + (size_t)(m0 + row) * D_ + (kt + 1) * 64 + cc * 8);
                cpa16(sbase + (boff + row * SP2 + cc * 4) * 4,
                      Wh + (size_t)(n0 + row) * D_ + (kt + 1) * 64 + cc * 8);
            }
            CPA_COMMIT();
        }
        const uint32_t* As = smp + (kt & 1) * TB_SZ;
        const uint32_t* Bs = smp + 2 * TB_SZ + (kt & 1) * TB_SZ;
#pragma unroll
        for (int kb = 0; kb < 4; kb++) {
            const int k0 = 8 * kb;
            uint32_t a[4][4];
#pragma unroll
            for (int mt = 0; mt < 4; mt++) {
                int r = wm * 64 + mt * 16 + g;
                a[mt][0] = As[r * SP2 + k0 + t];
                a[mt][1] = As[(r + 8) * SP2 + k0 + t];
                a[mt][2] = As[r * SP2 + k0 + t + 4];
                a[mt][3] = As[(r + 8) * SP2 + k0 + t + 4];
            }
#pragma unroll
            for (int nt = 0; nt < 8; nt++) {
                int n = wn * 64 + nt * 8 + g;
                uint32_t b[2];
                b[0] = Bs[n * SP2 + k0 + t];
                b[1] = Bs[n * SP2 + k0 + t + 4];
                MMA_F16(c[0][nt], a[0], b);
                MMA_F16(c[1][nt], a[1], b);
                MMA_F16(c[2][nt], a[2], b);
                MMA_F16(c[3][nt], a[3], b);
            }
        }
    }

    if (mode == 2) {
        __syncthreads();
        __half* stg = (__half*)smp;      // 128 cols x 136 halves
#pragma unroll
        for (int mt = 0; mt < 4; mt++) {
            int r0l = wm * 64 + mt * 16 + g;
            int r1l = r0l + 8;
#pragma unroll
            for (int nt = 0; nt < 8; nt++) {
                int cl = wn * 64 + nt * 8 + 2 * t;
                float2 bb = *(const float2*)&bias[n0 + cl];
                stg[cl * 136 + r0l]       = __float2half(c[mt][nt][0] + bb.x);
                stg[(cl + 1) * 136 + r0l] = __float2half(c[mt][nt][1] + bb.y);
                stg[cl * 136 + r1l]       = __float2half(c[mt][nt][2] + bb.x);
                stg[(cl + 1) * 136 + r1l] = __float2half(c[mt][nt][3] + bb.y);
            }
        }
        __syncthreads();
        int cgl = n0 + tid;
        int hh = cgl >> 6, hd = cgl & 63;
        int bb2 = m0 >> 11, l0 = m0 & 2047;
        __half* dst = g_VT + ((size_t)(bb2 * H_ + hh) * HD_ + hd) * L_ + l0;
#pragma unroll
        for (int q = 0; q < 16; q++)
            *(uint4*)(dst + q * 8) = *(const uint4*)&stg[tid * 136 + q * 8];
        __threadfence();
        __syncthreads();
        if (tid == 0) atomicAdd(&g_cV[(m_idx >> 4) * 8 + n_idx], 1);
        return;
    }

#pragma unroll
    for (int mt = 0; mt < 4; mt++) {
        int r0 = m0 + wm * 64 + mt * 16 + g;
        int r1 = r0 + 8;
#pragma unroll
        for (int nt = 0; nt < 8; nt++) {
            int col = n0 + wn * 64 + nt * 8 + 2 * t;
            float2 bb = *(const float2*)&bias[col];
            float v00 = c[mt][nt][0] + bb.x, v01 = c[mt][nt][1] + bb.y;
            float v10 = c[mt][nt][2] + bb.x, v11 = c[mt][nt][3] + bb.y;
            if (mode == 0) {
                v00 *= SCALE_Q; v01 *= SCALE_Q; v10 *= SCALE_Q; v11 *= SCALE_Q;
            }
            if (mode == 3) {
                *(float2*)&Cout[(size_t)r0 * D_ + col] = make_float2(v00, v01);
                *(float2*)&Cout[(size_t)r1 * D_ + col] = make_float2(v10, v11);
            } else {
                __half* dst = (mode == 0) ? g_Q : g_K;
                int hh = col >> 6, hd = col & 63;
                {
                    int bb2 = r0 >> 11, n = r0 & 2047;
                    *(__half2*)(dst + (((size_t)(bb2 * H_ + hh)) * 2048 + n) * HD_ + hd) =
                        __floats2half2_rn(v00, v01);
                }
                {
                    int bb2 = r1 >> 11, n = r1 & 2047;
                    *(__half2*)(dst + (((size_t)(bb2 * H_ + hh)) * 2048 + n) * HD_ + hd) =
                        __floats2half2_rn(v10, v11);
                }
            }
        }
    }
    if (mode != 3) {
        __threadfence();
        __syncthreads();
        if (tid == 0) {
            if (mode == 0) atomicAdd(&g_cQ[m_idx * 8 + n_idx], 1);
            else           atomicAdd(&g_cK[(m_idx >> 4) * 8 + n_idx], 1);
        }
    }
}

// ---------------------------------------------------------------------------
// Attention tile body (128q x (b,h); 4 warps; cp.async K/V double-buffered).
// ---------------------------------------------------------------------------
#define SK2 36
#define QS_SZ (128 * SK2)
#define KV_SZ (64 * SK2)

__device__ __forceinline__ void attn_body(int qt, int bh, uint32_t* smA)
{
    uint32_t* Qs = smA;
    uint32_t* Ksb = smA + QS_SZ;
    uint32_t* Vsb = smA + QS_SZ + 2 * KV_SZ;
    float* Mbb = (float*)(smA + QS_SZ + 4 * KV_SZ);
    const uint32_t sbase = smem_u32(smA);

    const int tid = threadIdx.x;
    const int lane = tid & 31, wid = tid >> 5;
    const int g = lane >> 2, t = lane & 3;
    const int b = bh >> 4, h = bh & 15;

    const __half* Qp = g_Q + ((size_t)bh * N_ + qt * 128) * HD_;
    const __half* Kp = g_K + (size_t)bh * L_ * HD_;
    const __half* Vtp = g_VT + (size_t)bh * HD_ * L_;
    const unsigned char* mp = g_mask + b * L_;

#pragma unroll
    for (int q = 0; q < 8; q++) {
        int idx = tid + 128 * q;
        int row = idx >> 3, cu = (idx & 7) * 4;
        *(uint4*)&Qs[row * SK2 + cu] = *(const uint4*)(Qp + (size_t)row * HD_ + (idx & 7) * 8);
    }

    auto issue_kv = [&](int tt, int s) {
#pragma unroll
        for (int q = 0; q < 4; q++) {
            int idx = tid + 128 * q;
            int row = idx >> 3, ch = idx & 7;
            cpa16(sbase + (QS_SZ + s * KV_SZ + row * SK2 + ch * 4) * 4,
                  Kp + (size_t)(tt * 64 + row) * HD_ + ch * 8);
            cpa16(sbase + (QS_SZ + 2 * KV_SZ + s * KV_SZ + row * SK2 + ch * 4) * 4,
                  Vtp + (size_t)row * L_ + tt * 64 + ch * 8);
        }
    };
    auto load_mb = [&](int tt, int s) {
        if (tid < 16) {
            uchar4 mv = *(const uchar4*)(mp + tt * 64 + tid * 4);
            float* Mb = Mbb + s * 64;
            Mb[tid * 4 + 0] = mv.x ? MASKBIAS : 0.0f;
            Mb[tid * 4 + 1] = mv.y ? MASKBIAS : 0.0f;
            Mb[tid * 4 + 2] = mv.z ? MASKBIAS : 0.0f;
            Mb[tid * 4 + 3] = mv.w ? MASKBIAS : 0.0f;
        }
    };

    issue_kv(0, 0); CPA_COMMIT();
    load_mb(0, 0);

    float m[4], l[4];
    float oc[2][8][4];
#pragma unroll
    for (int s = 0; s < 4; s++) { m[s] = MINIT; l[s] = 0.0f; }
#pragma unroll
    for (int mt = 0; mt < 2; mt++)
#pragma unroll
        for (int nt = 0; nt < 8; nt++)
#pragma unroll
            for (int j = 0; j < 4; j++) oc[mt][nt][j] = 0.0f;

    const int R = wid * 32;
    const int NT = L_ / 64;

#pragma unroll 1
    for (int tt = 0; tt < NT; tt++) {
        const int cb = tt & 1;
        CPA_WAIT0();
        __syncthreads();
        if (tt + 1 < NT) issue_kv(tt + 1, cb ^ 1);
        CPA_COMMIT();
        if (tt + 1 < NT) load_mb(tt + 1, cb ^ 1);

        const uint32_t* Ks = Ksb + cb * KV_SZ;
        const uint32_t* Vs = Vsb + cb * KV_SZ;
        const float* Mb = Mbb + cb * 64;

        float sc[2][8][4];
#pragma unroll
        for (int mt = 0; mt < 2; mt++)
#pragma unroll
            for (int nt = 0; nt < 8; nt++)
#pragma unroll
                for (int j = 0; j < 4; j++) sc[mt][nt][j] = 0.0f;
#pragma unroll
        for (int kb = 0; kb < 4; kb++) {
            const int k0 = 8 * kb;
            uint32_t aq[2][4];
#pragma unroll
            for (int mt = 0; mt < 2; mt++) {
                int r = R + mt * 16 + g;
                aq[mt][0] = Qs[r * SK2 + k0 + t];
                aq[mt][1] = Qs[(r + 8) * SK2 + k0 + t];
                aq[mt][2] = Qs[r * SK2 + k0 + t + 4];
                aq[mt][3] = Qs[(r + 8) * SK2 + k0 + t + 4];
            }
#pragma unroll
            for (int nt = 0; nt < 8; nt++) {
                int n = nt * 8 + g;
                uint32_t bk[2];
                bk[0] = Ks[n * SK2 + k0 + t];
                bk[1] = Ks[n * SK2 + k0 + t + 4];
                MMA_F16(sc[0][nt], aq[0], bk);
                MMA_F16(sc[1][nt], aq[1], bk);
            }
        }

#pragma unroll
        for (int nt = 0; nt < 8; nt++) {
            float2 mb = *(const float2*)&Mb[nt * 8 + 2 * t];
#pragma unroll
            for (int mt = 0; mt < 2; mt++) {
                sc[mt][nt][0] += mb.x; sc[mt][nt][1] += mb.y;
                sc[mt][nt][2] += mb.x; sc[mt][nt][3] += mb.y;
            }
        }

        float tm[4];
#pragma unroll
        for (int s = 0; s < 4; s++) tm[s] = -3.0e38f;
#pragma unroll
        for (int mt = 0; mt < 2; mt++)
#pragma unroll
            for (int nt = 0; nt < 8; nt++) {
                tm[mt * 2 + 0] = fmaxf(tm[mt * 2 + 0], fmaxf(sc[mt][nt][0], sc[mt][nt][1]));
                tm[mt * 2 + 1] = fmaxf(tm[mt * 2 + 1], fmaxf(sc[mt][nt][2], sc[mt][nt][3]));
            }
#pragma unroll
        for (int off = 1; off < 4; off <<= 1)
#pragma unroll
            for (int s = 0; s < 4; s++)
                tm[s] = fmaxf(tm[s], __shfl_xor_sync(0xffffffffu, tm[s], off));

        float al[4], rs[4];
#pragma unroll
        for (int s = 0; s < 4; s++) {
            float mn = fmaxf(m[s], tm[s]);
            al[s] = ex2f(m[s] - mn);
            m[s] = mn;
            rs[s] = 0.0f;
        }
#pragma unroll
        for (int mt = 0; mt < 2; mt++)
#pragma unroll
            for (int nt = 0; nt < 8; nt++) {
                sc[mt][nt][0] = ex2f(sc[mt][nt][0] - m[mt * 2 + 0]);
                sc[mt][nt][1] = ex2f(sc[mt][nt][1] - m[mt * 2 + 0]);
                sc[mt][nt][2] = ex2f(sc[mt][nt][2] - m[mt * 2 + 1]);
                sc[mt][nt][3] = ex2f(sc[mt][nt][3] - m[mt * 2 + 1]);
                rs[mt * 2 + 0] += sc[mt][nt][0] + sc[mt][nt][1];
                rs[mt * 2 + 1] += sc[mt][nt][2] + sc[mt][nt][3];
            }
#pragma unroll
        for (int off = 1; off < 4; off <<= 1)
#pragma unroll
            for (int s = 0; s < 4; s++)
                rs[s] += __shfl_xor_sync(0xffffffffu, rs[s], off);
#pragma unroll
        for (int s = 0; s < 4; s++) l[s] = l[s] * al[s] + rs[s];
#pragma unroll
        for (int mt = 0; mt < 2; mt++)
#pragma unroll
            for (int nt = 0; nt < 8; nt++) {
                oc[mt][nt][0] *= al[mt * 2 + 0]; oc[mt][nt][1] *= al[mt * 2 + 0];
                oc[mt][nt][2] *= al[mt * 2 + 1]; oc[mt][nt][3] *= al[mt * 2 + 1];
            }

#pragma unroll
        for (int j = 0; j < 4; j++) {
            const int k0 = 8 * j;
            uint32_t ap[2][4];
#pragma unroll
            for (int mt = 0; mt < 2; mt++) {
                ap[mt][0] = h2pack(sc[mt][2 * j][0], sc[mt][2 * j][1]);
                ap[mt][1] = h2pack(sc[mt][2 * j][2], sc[mt][2 * j][3]);
                ap[mt][2] = h2pack(sc[mt][2 * j + 1][0], sc[mt][2 * j + 1][1]);
                ap[mt][3] = h2pack(sc[mt][2 * j + 1][2], sc[mt][2 * j + 1][3]);
            }
#pragma unroll
            for (int nt = 0; nt < 8; nt++) {
                int n = nt * 8 + g;
                uint32_t bv[2];
                bv[0] = Vs[n * SK2 + k0 + t];
                bv[1] = Vs[n * SK2 + k0 + t + 4];
                MMA_F16(oc[0][nt], ap[0], bv);
                MMA_F16(oc[1][nt], ap[1], bv);
            }
        }
    }

    float inv[4];
#pragma unroll
    for (int s = 0; s < 4; s++) inv[s] = 1.0f / l[s];
#pragma unroll
    for (int mt = 0; mt < 2; mt++) {
        int n0r = qt * 128 + R + mt * 16 + g;
        int n1r = n0r + 8;
#pragma unroll
        for (int nt = 0; nt < 8; nt++) {
            int cc = nt * 8 + 2 * t;
            *(__half2*)(g_O + ((size_t)(b * N_ + n0r)) * D_ + h * HD_ + cc) =
                __floats2half2_rn(oc[mt][nt][0] * inv[mt * 2 + 0],
                                  oc[mt][nt][1] * inv[mt * 2 + 0]);
            *(__half2*)(g_O + ((size_t)(b * N_ + n1r)) * D_ + h * HD_ + cc) =
                __floats2half2_rn(oc[mt][nt][2] * inv[mt * 2 + 1],
                                  oc[mt][nt][3] * inv[mt * 2 + 1]);
        }
    }
    __threadfence();
    __syncthreads();
    if (tid == 0) atomicAdd(&g_cA[b * 16 + qt], 1);
}

// ---------------------------------------------------------------------------
// Megakernel: blocks [0,768) QKV (column-major), [768,1280) attention,
// [1280,1536) out-projection. Flag-based dataflow absorbs phase tails.
// ---------------------------------------------------------------------------
__global__ void __launch_bounds__(128, 2)
mega(const float* __restrict__ b0, const float* __restrict__ b1,
     const float* __restrict__ b2, const float* __restrict__ b3,
     float* __restrict__ Cout)
{
    extern __shared__ uint32_t smp[];
    const int id = blockIdx.x;
    const int tid = threadIdx.x;

    if (id < 768) {
        // QKV: column-major order so head-columns complete early
        int n_idx = id / 96;
        int rem = id % 96;
        int mode = rem / 32;
        int m_idx = rem % 32;
        proj_body(mode, m_idx, n_idx, smp, b0, b1, b2, b3, nullptr);
    } else if (id < 1280) {
        int a = id - 768;
        int n_pair = a / 64;         // head column (2 heads per 128-col tile)
        int rem = a % 64;
        int hsel = rem & 1;
        int b = (rem >> 1) & 1;
        int qt = rem >> 2;
        int h = n_pair * 2 + hsel;
        int bh = b * 16 + h;
        if (tid == 0) {
            spin_ge(&g_cQ[(b * 16 + qt) * 8 + n_pair], 1);
            spin_ge(&g_cK[b * 8 + n_pair], 16);
            spin_ge(&g_cV[b * 8 + n_pair], 16);
            __threadfence();
        }
        __syncthreads();
        attn_body(qt, bh, smp);
    } else {
        int o = id - 1280;
        int m_idx = o & 31;
        int n_idx = o >> 5;
        if (tid == 0) {
            spin_ge(&g_cA[m_idx], 16);
            __threadfence();
        }
        __syncthreads();
        proj_body(3, m_idx, n_idx, smp, b0, b1, b2, b3, Cout);
    }
}

// ---------------------------------------------------------------------------
extern "C" void kernel_launch(void* const* d_in, const int* in_sizes, int n_in,
                              void* d_out, int out_size)
{
    (void)in_sizes; (void)n_in; (void)out_size;
    const float* x_q  = (const float*)d_in[0];
    const float* x_kv = (const float*)d_in[1];
    const void*  mraw = d_in[2];
    const float* wq = (const float*)d_in[3];
    const float* bq = (const float*)d_in[4];
    const float* wk = (const float*)d_in[5];
    const float* bk = (const float*)d_in[6];
    const float* wv = (const float*)d_in[7];
    const float* bv = (const float*)d_in[8];
    const float* wo = (const float*)d_in[9];
    const float* bo = (const float*)d_in[10];
    float* out = (float*)d_out;

    static int attr_done = 0;
    if (!attr_done) {
        cudaFuncSetAttribute(mega, cudaFuncAttributeMaxDynamicSharedMemorySize, PR_SMEM);
        attr_done = 1;
    }

    prep<<<8193, 256>>>(x_q, x_kv, wq, wk, wv, wo, mraw);
    mega<<<1536, 128, PR_SMEM>>>(bq, bk, bv, bo, out);
}